// round 6
// baseline (speedup 1.0000x reference)
#include <cuda_runtime.h>
#include <cuda_bf16.h>
#include <cstddef>

// ---------------------------------------------------------------------------
// RoutedAllFC round 2: fp32 FFMA2 conv stack with multi-pixel-per-thread
// (PX) to raise FMA:LDS ratio; conv4 CI-split into 4 partial pre-pool slices
// (no atomics) with finalize fused into the BN kernel.
// ---------------------------------------------------------------------------

#define B_   64
#define CH_  160
#define EPS_ 1e-5f

__device__ float g_y1[B_ * CH_ * 32 * 32];
__device__ float g_y2[B_ * CH_ * 16 * 16];
__device__ float g_y3[B_ * CH_ * 8 * 8];
__device__ float g_pre4[4][B_ * CH_ * 8 * 8];   // conv4 partial pre-pool slices
__device__ float g_feat[B_ * 2560];
__device__ float g_h1[B_ * 320];
__device__ float g_h2[B_ * 320];

// ---- packed f32x2 helpers --------------------------------------------------
__device__ __forceinline__ unsigned long long pk2(float x) {
    unsigned long long r;
    asm("mov.b64 %0, {%1, %1};" : "=l"(r) : "f"(x));
    return r;
}
__device__ __forceinline__ void ffma2(unsigned long long& d,
                                      unsigned long long a,
                                      unsigned long long b) {
    asm("fma.rn.f32x2 %0, %1, %2, %3;" : "=l"(d) : "l"(a), "l"(b), "l"(d));
}
__device__ __forceinline__ float2 unpk(unsigned long long v) {
    float2 f;
    asm("mov.b64 {%0, %1}, %2;" : "=f"(f.x), "=f"(f.y) : "l"(v));
    return f;
}

// ---------------------------------------------------------------------------
// Fused conv3x3(pad1)+bias+ReLU+maxpool2. Thread owns PX adjacent pooled
// pixels (x-direction) for CO_T output channels (as f32x2 channel pairs), so
// each weight LDS.64 feeds 4*PX FFMA2s.
// ---------------------------------------------------------------------------
template <int CI, int HIN, int WIN, int THP, int TWPT, int PX, int CG,
          int CO_T, int CICH>
__global__ void __launch_bounds__(THP * TWPT * CG)
conv_pool(const float* __restrict__ in, const float* __restrict__ Wt,
          const float* __restrict__ bias, float* __restrict__ out) {
    constexpr int CO = 160;
    constexpr int HP = HIN / 2, WP = WIN / 2;
    constexpr int TWP = TWPT * PX;          // pooled tile width
    constexpr int TH = 2 * THP, TW = 2 * TWP;
    constexpr int SH = TH + 2, SWD = TW + 2;
    constexpr int T = THP * TWPT * CG;
    constexpr int CO_BLK = CG * CO_T;
    constexpr int NP = CO_T / 2;
    static_assert(CO_T % 2 == 0, "channel pairing requires even CO_T");

    __shared__ float s_in[CICH][SH][SWD];
    __shared__ float s_w[CICH][9][CO_BLK];

    const int tid = threadIdx.x;
    const int cg   = tid / (THP * TWPT);
    const int pix  = tid % (THP * TWPT);
    const int lpy  = pix / TWPT, lpxt = pix % TWPT;
    const int nimg = blockIdx.z;
    const int cob0 = blockIdx.y * CO_BLK;
    constexpr int TILESX = WP / TWP;
    const int tpy0 = (blockIdx.x / TILESX) * THP;
    const int tpx0 = (blockIdx.x % TILESX) * TWP;
    const int iy0 = 2 * tpy0 - 1, ix0 = 2 * tpx0 - 1;

    unsigned long long acc[NP][PX][4];
#pragma unroll
    for (int p = 0; p < NP; p++)
#pragma unroll
        for (int px = 0; px < PX; px++)
#pragma unroll
            for (int q = 0; q < 4; q++) acc[p][px][4 - 4 + q] = 0ull;

    for (int cc = 0; cc < CI; cc += CICH) {
        __syncthreads();
        for (int idx = tid; idx < CICH * SH * SWD; idx += T) {
            int cl  = idx / (SH * SWD);
            int rem = idx - cl * (SH * SWD);
            int iy  = rem / SWD, ix = rem - iy * SWD;
            int gy = iy0 + iy, gx = ix0 + ix;
            float v = 0.f;
            if ((unsigned)gy < (unsigned)HIN && (unsigned)gx < (unsigned)WIN)
                v = in[(((size_t)nimg * CI + (cc + cl)) * HIN + gy) * WIN + gx];
            (&s_in[0][0][0])[idx] = v;
        }
        for (int idx = tid; idx < CICH * 9 * CO_BLK; idx += T) {
            int cl  = idx / (9 * CO_BLK);
            int rem = idx - cl * (9 * CO_BLK);
            int k   = rem / CO_BLK;
            int col = rem - k * CO_BLK;
            (&s_w[0][0][0])[idx] =
                Wt[((size_t)(cob0 + col) * CI + (cc + cl)) * 9 + k];
        }
        __syncthreads();

#pragma unroll
        for (int cl = 0; cl < CICH; cl++) {
            const float* sp = &s_in[cl][2 * lpy][2 * lpxt * PX];
            float ip[4][2 * PX + 2];
#pragma unroll
            for (int r = 0; r < 4; r++)
#pragma unroll
                for (int c = 0; c <= PX; c++) {
                    float2 a = *(const float2*)(sp + r * SWD + 2 * c);
                    ip[r][2 * c] = a.x;
                    ip[r][2 * c + 1] = a.y;
                }
#pragma unroll
            for (int ky = 0; ky < 3; ky++)
#pragma unroll
                for (int kx = 0; kx < 3; kx++) {
                    const float* wp = &s_w[cl][ky * 3 + kx][cg * CO_T];
                    unsigned long long w2[NP];
#pragma unroll
                    for (int p = 0; p < NP; p++)
                        w2[p] = *(const unsigned long long*)(wp + 2 * p);
#pragma unroll
                    for (int px = 0; px < PX; px++) {
                        unsigned long long i00 = pk2(ip[ky][kx + 2 * px]);
                        unsigned long long i01 = pk2(ip[ky][kx + 2 * px + 1]);
                        unsigned long long i10 = pk2(ip[ky + 1][kx + 2 * px]);
                        unsigned long long i11 = pk2(ip[ky + 1][kx + 2 * px + 1]);
#pragma unroll
                        for (int p = 0; p < NP; p++) {
                            ffma2(acc[p][px][0], w2[p], i00);
                            ffma2(acc[p][px][1], w2[p], i01);
                            ffma2(acc[p][px][2], w2[p], i10);
                            ffma2(acc[p][px][3], w2[p], i11);
                        }
                    }
                }
        }
    }

#pragma unroll
    for (int p = 0; p < NP; p++) {
        int co = cob0 + cg * CO_T + 2 * p;
        float blo = bias[co], bhi = bias[co + 1];
#pragma unroll
        for (int px = 0; px < PX; px++) {
            float2 m0 = unpk(acc[p][px][0]), m1 = unpk(acc[p][px][1]);
            float2 m2 = unpk(acc[p][px][2]), m3 = unpk(acc[p][px][3]);
            float lo = fmaxf(fmaxf(m0.x, m1.x), fmaxf(m2.x, m3.x)) + blo;
            float hi = fmaxf(fmaxf(m0.y, m1.y), fmaxf(m2.y, m3.y)) + bhi;
            lo = fmaxf(lo, 0.f);
            hi = fmaxf(hi, 0.f);
            size_t ob = (((size_t)nimg * CO + co) * HP + (tpy0 + lpy)) * WP +
                        (tpx0 + lpxt * PX + px);
            out[ob] = lo;
            out[ob + (size_t)HP * WP] = hi;
        }
    }
}

// ---------------------------------------------------------------------------
// conv4 partial: CI split across blockIdx.x into 4 slices of 40 channels.
// Stores raw pre-pool conv partial sums (no bias/relu/pool) to its own slice.
// 128 thr = 8 pixthreads (4 pooled rows x 2 x-pairs, PX=2) x 16 cg (CO_T=2).
// ---------------------------------------------------------------------------
__global__ void __launch_bounds__(128)
conv4_part(const float* __restrict__ in, const float* __restrict__ Wt,
           float* __restrict__ pre) {
    constexpr int CI = 160, CIS = 40, CICH = 8, CO = 160, CO_BLK = 32;
    __shared__ float s_in[CICH][10][10];
    __shared__ float s_w[CICH][9][CO_BLK];

    const int tid = threadIdx.x;
    const int cg = tid / 8;            // 16 channel groups, 2 ch each
    const int pixt = tid % 8;
    const int lpy = pixt / 2, lpxt = pixt % 2;   // pooled row, x-pair id
    const int ci0 = blockIdx.x * CIS;
    const int cob0 = blockIdx.y * CO_BLK;
    const int nimg = blockIdx.z;
    float* slice = pre + (size_t)blockIdx.x * (B_ * CH_ * 64);

    unsigned long long acc[2][4];      // [px][tap]
#pragma unroll
    for (int px = 0; px < 2; px++)
#pragma unroll
        for (int q = 0; q < 4; q++) acc[px][q] = 0ull;

    for (int cc = 0; cc < CIS; cc += CICH) {
        __syncthreads();
        for (int idx = tid; idx < CICH * 100; idx += 128) {
            int cl = idx / 100, rem = idx - cl * 100;
            int iy = rem / 10, ix = rem - iy * 10;
            int gy = iy - 1, gx = ix - 1;
            float v = 0.f;
            if ((unsigned)gy < 8u && (unsigned)gx < 8u)
                v = in[(((size_t)nimg * CI + (ci0 + cc + cl)) * 8 + gy) * 8 + gx];
            (&s_in[0][0][0])[idx] = v;
        }
        for (int idx = tid; idx < CICH * 9 * CO_BLK; idx += 128) {
            int cl = idx / (9 * CO_BLK);
            int rem = idx - cl * (9 * CO_BLK);
            int k = rem / CO_BLK, col = rem - k * CO_BLK;
            (&s_w[0][0][0])[idx] =
                Wt[((size_t)(cob0 + col) * CI + (ci0 + cc + cl)) * 9 + k];
        }
        __syncthreads();

#pragma unroll
        for (int cl = 0; cl < CICH; cl++) {
            const float* sp = &s_in[cl][2 * lpy][4 * lpxt];
            float ip[4][6];
#pragma unroll
            for (int r = 0; r < 4; r++)
#pragma unroll
                for (int c = 0; c < 3; c++) {
                    float2 a = *(const float2*)(sp + r * 10 + 2 * c);
                    ip[r][2 * c] = a.x;
                    ip[r][2 * c + 1] = a.y;
                }
#pragma unroll
            for (int ky = 0; ky < 3; ky++)
#pragma unroll
                for (int kx = 0; kx < 3; kx++) {
                    unsigned long long w2 = *(const unsigned long long*)
                        (&s_w[cl][ky * 3 + kx][cg * 2]);
#pragma unroll
                    for (int px = 0; px < 2; px++) {
                        unsigned long long i00 = pk2(ip[ky][kx + 2 * px]);
                        unsigned long long i01 = pk2(ip[ky][kx + 2 * px + 1]);
                        unsigned long long i10 = pk2(ip[ky + 1][kx + 2 * px]);
                        unsigned long long i11 = pk2(ip[ky + 1][kx + 2 * px + 1]);
                        ffma2(acc[px][0], w2, i00);
                        ffma2(acc[px][1], w2, i01);
                        ffma2(acc[px][2], w2, i10);
                        ffma2(acc[px][3], w2, i11);
                    }
                }
        }
    }

    // store pre-pool partials: taps (dy,dx) at (2*py+dy, 2*pxp+dx), ch pair.
    int co = cob0 + cg * 2;
#pragma unroll
    for (int px = 0; px < 2; px++) {
        int pxp = lpxt * 2 + px;   // pooled x 0..3
#pragma unroll
        for (int dy = 0; dy < 2; dy++)
#pragma unroll
            for (int dx = 0; dx < 2; dx++) {
                float2 v = unpk(acc[px][dy * 2 + dx]);
                size_t a = (((size_t)nimg * CO + co) * 8 + (2 * lpy + dy)) * 8 +
                           (2 * pxp + dx);
                slice[a] = v.x;
                slice[a + 64] = v.y;   // next channel plane (8*8)
            }
    }
}

// ---------------------------------------------------------------------------
// Fused conv4 finalize (sum 4 CI-slices, +bias, ReLU, maxpool2) + BatchNorm
// (batch stats) + affine + flatten. One block per channel, 1024 values.
// ---------------------------------------------------------------------------
__global__ void __launch_bounds__(256)
bn_finalize(const float* __restrict__ pre, const float* __restrict__ b4,
            const float* __restrict__ gamma, const float* __restrict__ beta,
            float* __restrict__ feat) {
    constexpr size_t SL = (size_t)B_ * CH_ * 64;
    int c = blockIdx.x, tid = threadIdx.x;
    float bc = b4[c];
    int g0 = tid * 4;
    int n = g0 >> 4;
    float v[4];
#pragma unroll
    for (int j = 0; j < 4; j++) {
        int g = g0 + j;
        int pp = g & 15;
        int py = pp >> 2, px = pp & 3;
        size_t base = (((size_t)n * CH_ + c) * 8 + 2 * py) * 8 + 2 * px;
        float s00 = 0.f, s01 = 0.f, s10 = 0.f, s11 = 0.f;
#pragma unroll
        for (int s = 0; s < 4; s++) {
            float2 r0 = *(const float2*)(pre + s * SL + base);
            float2 r1 = *(const float2*)(pre + s * SL + base + 8);
            s00 += r0.x; s01 += r0.y; s10 += r1.x; s11 += r1.y;
        }
        float m = fmaxf(fmaxf(s00, s01), fmaxf(s10, s11)) + bc;
        v[j] = fmaxf(m, 0.f);
    }
    float s = v[0] + v[1] + v[2] + v[3];
    float q = v[0] * v[0] + v[1] * v[1] + v[2] * v[2] + v[3] * v[3];
#pragma unroll
    for (int off = 16; off; off >>= 1) {
        s += __shfl_xor_sync(0xffffffffu, s, off);
        q += __shfl_xor_sync(0xffffffffu, q, off);
    }
    __shared__ float rs[8], rq[8];
    __shared__ float s_scale, s_shift;
    int w = tid >> 5, lane = tid & 31;
    if (!lane) { rs[w] = s; rq[w] = q; }
    __syncthreads();
    if (tid == 0) {
        float S = 0.f, Q = 0.f;
#pragma unroll
        for (int j = 0; j < 8; j++) { S += rs[j]; Q += rq[j]; }
        float mean = S * (1.f / 1024.f);
        float var  = Q * (1.f / 1024.f) - mean * mean;
        float r = rsqrtf(var + EPS_);
        float gm = gamma[c] * r;
        s_scale = gm;
        s_shift = beta[c] - mean * gm;
    }
    __syncthreads();
    float gm = s_scale, bt = s_shift;
    float4 o = make_float4(v[0] * gm + bt, v[1] * gm + bt,
                           v[2] * gm + bt, v[3] * gm + bt);
    *(float4*)(feat + (size_t)n * 2560 + c * 16 + (g0 & 15)) = o;
}

// ---------------------------------------------------------------------------
// Routed linear: warp per output element.
// ---------------------------------------------------------------------------
template <bool RELU>
__global__ void __launch_bounds__(256)
fc_routed(const float* __restrict__ X, const float* __restrict__ Wb,
          const float* __restrict__ Bb, const int* __restrict__ act,
          float* __restrict__ Y, int IN, int OD) {
    int n = blockIdx.y;
    int w = threadIdx.x >> 5, lane = threadIdx.x & 31;
    int o = blockIdx.x * (blockDim.x >> 5) + w;
    if (o >= OD) return;
    int e = act[n];
    const float* wr = Wb + ((size_t)e * OD + o) * IN;
    const float* xr = X + (size_t)n * IN;
    float s = 0.f;
    for (int i = lane * 4; i < IN; i += 128) {
        float4 a = *(const float4*)(wr + i);
        float4 b = *(const float4*)(xr + i);
        s += a.x * b.x + a.y * b.y + a.z * b.z + a.w * b.w;
    }
#pragma unroll
    for (int off = 16; off; off >>= 1) s += __shfl_xor_sync(0xffffffffu, s, off);
    if (!lane) {
        float v = s + Bb[(size_t)e * OD + o];
        if (RELU) v = fmaxf(v, 0.f);
        Y[(size_t)n * OD + o] = v;
    }
}

// ---------------------------------------------------------------------------
extern "C" void kernel_launch(void* const* d_in, const int* in_sizes, int n_in,
                              void* d_out, int out_size) {
    const float* x   = (const float*)d_in[0];
    const int* a1    = (const int*)d_in[1];
    const int* a2    = (const int*)d_in[2];
    const int* a3    = (const int*)d_in[3];
    const float* W1  = (const float*)d_in[4];
    const float* b1  = (const float*)d_in[5];
    const float* W2  = (const float*)d_in[6];
    const float* b2  = (const float*)d_in[7];
    const float* W3  = (const float*)d_in[8];
    const float* b3  = (const float*)d_in[9];
    const float* W4  = (const float*)d_in[10];
    const float* b4  = (const float*)d_in[11];
    const float* gam = (const float*)d_in[12];
    const float* bet = (const float*)d_in[13];
    const float* E1W = (const float*)d_in[14];
    const float* E1b = (const float*)d_in[15];
    const float* E2W = (const float*)d_in[16];
    const float* E2b = (const float*)d_in[17];
    const float* E3W = (const float*)d_in[18];
    const float* E3b = (const float*)d_in[19];
    float* out = (float*)d_out;

    float *y1, *y2, *y3, *pre4, *feat, *h1, *h2;
    cudaGetSymbolAddress((void**)&y1, g_y1);
    cudaGetSymbolAddress((void**)&y2, g_y2);
    cudaGetSymbolAddress((void**)&y3, g_y3);
    cudaGetSymbolAddress((void**)&pre4, g_pre4);
    cudaGetSymbolAddress((void**)&feat, g_feat);
    cudaGetSymbolAddress((void**)&h1, g_h1);
    cudaGetSymbolAddress((void**)&h2, g_h2);

    // conv1: 3->160, 64x64 -> pooled 32x32; PX=1, CO_BLK=8.
    conv_pool<3, 64, 64, 16, 16, 1, 1, 8, 3>
        <<<dim3(4, 20, 64), 256>>>(x, W1, b1, y1);
    // conv2: 160->160, 32x32 -> 16x16; PX=2, CG=2, CO_T=8 -> CO_BLK=16.
    conv_pool<160, 32, 32, 16, 8, 2, 2, 8, 8>
        <<<dim3(1, 10, 64), 256>>>(y1, W2, b2, y2);
    // conv3: 160->160, 16x16 -> 8x8; PX=2, CG=4, CO_T=4 -> CO_BLK=16.
    conv_pool<160, 16, 16, 8, 4, 2, 4, 4, 8>
        <<<dim3(1, 10, 64), 128>>>(y2, W3, b3, y3);
    // conv4 partials: CI split x4, CO_BLK=32.
    conv4_part<<<dim3(4, 5, 64), 128>>>(y3, W4, pre4);
    // finalize conv4 + BN + flatten.
    bn_finalize<<<160, 256>>>(pre4, b4, gam, bet, feat);

    fc_routed<true ><<<dim3(40, 64), 256>>>(feat, E1W, E1b, a1, h1, 2560, 320);
    fc_routed<true ><<<dim3(40, 64), 256>>>(h1,   E2W, E2b, a2, h2, 320, 320);
    fc_routed<false><<<dim3(2, 64),  256>>>(h2,   E3W, E3b, a3, out, 320, 10);
}

// round 8
// speedup vs baseline: 1.0765x; 1.0765x over previous
#include <cuda_runtime.h>
#include <cuda_bf16.h>
#include <cstddef>

// ---------------------------------------------------------------------------
// RoutedAllFC round 8: round-7 design (hoisted/deduped f32x2 packing,
// warp-broadcast weights, high-ILP conv4) with ALIGNMENT FIX: smem row
// strides kept even so float2 (LDS.64) loads stay 8B-aligned.
// ---------------------------------------------------------------------------

#define B_   64
#define CH_  160
#define EPS_ 1e-5f

__device__ float g_y1[B_ * CH_ * 32 * 32];
__device__ float g_y2[B_ * CH_ * 16 * 16];
__device__ float g_y3[B_ * CH_ * 8 * 8];
__device__ float g_pre4[4][B_ * CH_ * 8 * 8];
__device__ float g_feat[B_ * 2560];
__device__ float g_h1[B_ * 320];
__device__ float g_h2[B_ * 320];

// ---- packed f32x2 helpers --------------------------------------------------
__device__ __forceinline__ unsigned long long pk2(float x) {
    unsigned long long r;
    asm("mov.b64 %0, {%1, %1};" : "=l"(r) : "f"(x));
    return r;
}
__device__ __forceinline__ void ffma2(unsigned long long& d,
                                      unsigned long long a,
                                      unsigned long long b) {
    asm("fma.rn.f32x2 %0, %1, %2, %3;" : "=l"(d) : "l"(a), "l"(b), "l"(d));
}
__device__ __forceinline__ float2 unpk(unsigned long long v) {
    float2 f;
    asm("mov.b64 {%0, %1}, %2;" : "=f"(f.x), "=f"(f.y) : "l"(v));
    return f;
}

// ---------------------------------------------------------------------------
// Fused conv3x3(pad1)+bias+ReLU+maxpool2.
// THP*TWPT == 32: each warp is one channel group -> weight LDS.64 broadcasts.
// SWD is even (TW+2) so all float2 smem loads are 8B-aligned.
// ---------------------------------------------------------------------------
template <int CI, int HIN, int WIN, int THP, int TWPT, int PX, int CG,
          int CO_T, int CICH>
__global__ void __launch_bounds__(THP * TWPT * CG)
conv_pool(const float* __restrict__ in, const float* __restrict__ Wt,
          const float* __restrict__ bias, float* __restrict__ out) {
    constexpr int CO = 160;
    constexpr int HP = HIN / 2, WP = WIN / 2;
    constexpr int TWP = TWPT * PX;
    constexpr int TH = 2 * THP, TW = 2 * TWP;
    constexpr int SH = TH + 2;
    constexpr int SWD = TW + 2;                 // even -> aligned LDS.64
    constexpr int T = THP * TWPT * CG;
    constexpr int CO_BLK = CG * CO_T;
    constexpr int NP = CO_T / 2;
    constexpr int IC = 2 * PX + 2;
    static_assert(THP * TWPT == 32, "warp must equal one channel group");
    static_assert(CO_T % 2 == 0, "channel pairing requires even CO_T");
    static_assert(SWD % 2 == 0, "row stride must keep float2 aligned");

    __shared__ float s_in[CICH][SH][SWD];
    __shared__ float s_w[CICH][9][CO_BLK];

    const int tid = threadIdx.x;
    const int cg   = tid / 32;
    const int pix  = tid % 32;
    const int lpy  = pix / TWPT, lpxt = pix % TWPT;
    const int nimg = blockIdx.z;
    const int cob0 = blockIdx.y * CO_BLK;
    constexpr int TILESX = WP / TWP;
    const int tpy0 = (blockIdx.x / TILESX) * THP;
    const int tpx0 = (blockIdx.x % TILESX) * TWP;
    const int iy0 = 2 * tpy0 - 1, ix0 = 2 * tpx0 - 1;

    unsigned long long acc[NP][PX][4];
#pragma unroll
    for (int p = 0; p < NP; p++)
#pragma unroll
        for (int px = 0; px < PX; px++)
#pragma unroll
            for (int q = 0; q < 4; q++) acc[p][px][q] = 0ull;

    for (int cc = 0; cc < CI; cc += CICH) {
        __syncthreads();
        for (int idx = tid; idx < CICH * SH * SWD; idx += T) {
            int cl  = idx / (SH * SWD);
            int rem = idx - cl * (SH * SWD);
            int iy  = rem / SWD, ix = rem - iy * SWD;
            int gy = iy0 + iy, gx = ix0 + ix;
            float v = 0.f;
            if ((unsigned)gy < (unsigned)HIN && (unsigned)gx < (unsigned)WIN)
                v = in[(((size_t)nimg * CI + (cc + cl)) * HIN + gy) * WIN + gx];
            (&s_in[0][0][0])[idx] = v;
        }
        for (int idx = tid; idx < CICH * 9 * CO_BLK; idx += T) {
            int cl  = idx / (9 * CO_BLK);
            int rem = idx - cl * (9 * CO_BLK);
            int k   = rem / CO_BLK;
            int col = rem - k * CO_BLK;
            (&s_w[0][0][0])[idx] =
                Wt[((size_t)(cob0 + col) * CI + (cc + cl)) * 9 + k];
        }
        __syncthreads();

#pragma unroll
        for (int cl = 0; cl < CICH; cl++) {
            // hoisted, deduped broadcast packs: 4 rows x IC cols, once per cl
            const float* sp = &s_in[cl][2 * lpy][2 * lpxt * PX];
            unsigned long long ippk[4][IC];
#pragma unroll
            for (int r = 0; r < 4; r++)
#pragma unroll
                for (int c = 0; c <= PX; c++) {
                    float2 a = *(const float2*)(sp + r * SWD + 2 * c);
                    ippk[r][2 * c]     = pk2(a.x);
                    ippk[r][2 * c + 1] = pk2(a.y);
                }
#pragma unroll
            for (int ky = 0; ky < 3; ky++)
#pragma unroll
                for (int kx = 0; kx < 3; kx++) {
                    const float* wp = &s_w[cl][ky * 3 + kx][cg * CO_T];
                    unsigned long long w2[NP];
#pragma unroll
                    for (int p = 0; p < NP; p++)
                        w2[p] = *(const unsigned long long*)(wp + 2 * p);
#pragma unroll
                    for (int px = 0; px < PX; px++) {
#pragma unroll
                        for (int p = 0; p < NP; p++) {
                            ffma2(acc[p][px][0], w2[p], ippk[ky][kx + 2 * px]);
                            ffma2(acc[p][px][1], w2[p], ippk[ky][kx + 2 * px + 1]);
                            ffma2(acc[p][px][2], w2[p], ippk[ky + 1][kx + 2 * px]);
                            ffma2(acc[p][px][3], w2[p], ippk[ky + 1][kx + 2 * px + 1]);
                        }
                    }
                }
        }
    }

#pragma unroll
    for (int p = 0; p < NP; p++) {
        int co = cob0 + cg * CO_T + 2 * p;
        float blo = bias[co], bhi = bias[co + 1];
#pragma unroll
        for (int px = 0; px < PX; px++) {
            float2 m0 = unpk(acc[p][px][0]), m1 = unpk(acc[p][px][1]);
            float2 m2 = unpk(acc[p][px][2]), m3 = unpk(acc[p][px][3]);
            float lo = fmaxf(fmaxf(m0.x, m1.x), fmaxf(m2.x, m3.x)) + blo;
            float hi = fmaxf(fmaxf(m0.y, m1.y), fmaxf(m2.y, m3.y)) + bhi;
            lo = fmaxf(lo, 0.f);
            hi = fmaxf(hi, 0.f);
            size_t ob = (((size_t)nimg * CO + co) * HP + (tpy0 + lpy)) * WP +
                        (tpx0 + lpxt * PX + px);
            out[ob] = lo;
            out[ob + (size_t)HP * WP] = hi;
        }
    }
}

// ---------------------------------------------------------------------------
// conv4 partial: CI split x4 into pre-pool partial sums. T=64, CO_T=4 (NP=2),
// hoisted packs. SWD=10 (even) for aligned float2.
// ---------------------------------------------------------------------------
__global__ void __launch_bounds__(64)
conv4_part(const float* __restrict__ in, const float* __restrict__ Wt,
           float* __restrict__ pre) {
    constexpr int CI = 160, CIS = 40, CICH = 8, CO = 160, CO_BLK = 32;
    constexpr int SWD = 10;
    __shared__ float s_in[CICH][10][SWD];
    __shared__ float s_w[CICH][9][CO_BLK];

    const int tid = threadIdx.x;
    const int cg = tid >> 3;            // 8 groups of 4 channels
    const int pixt = tid & 7;
    const int lpy = pixt >> 1, lpxt = pixt & 1;
    const int ci0 = blockIdx.x * CIS;
    const int cob0 = blockIdx.y * CO_BLK;
    const int nimg = blockIdx.z;
    float* slice = pre + (size_t)blockIdx.x * (B_ * CH_ * 64);

    unsigned long long acc[2][2][4];    // [p][px][tap]
#pragma unroll
    for (int p = 0; p < 2; p++)
#pragma unroll
        for (int px = 0; px < 2; px++)
#pragma unroll
            for (int q = 0; q < 4; q++) acc[p][px][q] = 0ull;

    for (int cc = 0; cc < CIS; cc += CICH) {
        __syncthreads();
        for (int idx = tid; idx < CICH * 10 * SWD; idx += 64) {
            int cl = idx / (10 * SWD), rem = idx - cl * (10 * SWD);
            int iy = rem / SWD, ix = rem - iy * SWD;
            int gy = iy - 1, gx = ix - 1;
            float v = 0.f;
            if ((unsigned)gy < 8u && (unsigned)gx < 8u)
                v = in[(((size_t)nimg * CI + (ci0 + cc + cl)) * 8 + gy) * 8 + gx];
            (&s_in[0][0][0])[idx] = v;
        }
        for (int idx = tid; idx < CICH * 9 * CO_BLK; idx += 64) {
            int cl = idx / (9 * CO_BLK);
            int rem = idx - cl * (9 * CO_BLK);
            int k = rem / CO_BLK, col = rem - k * CO_BLK;
            (&s_w[0][0][0])[idx] =
                Wt[((size_t)(cob0 + col) * CI + (ci0 + cc + cl)) * 9 + k];
        }
        __syncthreads();

#pragma unroll
        for (int cl = 0; cl < CICH; cl++) {
            const float* sp = &s_in[cl][2 * lpy][4 * lpxt];
            unsigned long long ippk[4][6];
#pragma unroll
            for (int r = 0; r < 4; r++)
#pragma unroll
                for (int c = 0; c < 3; c++) {
                    float2 a = *(const float2*)(sp + r * SWD + 2 * c);
                    ippk[r][2 * c]     = pk2(a.x);
                    ippk[r][2 * c + 1] = pk2(a.y);
                }
#pragma unroll
            for (int ky = 0; ky < 3; ky++)
#pragma unroll
                for (int kx = 0; kx < 3; kx++) {
                    const float* wp = &s_w[cl][ky * 3 + kx][cg * 4];
                    unsigned long long w2[2];
                    w2[0] = *(const unsigned long long*)(wp);
                    w2[1] = *(const unsigned long long*)(wp + 2);
#pragma unroll
                    for (int px = 0; px < 2; px++) {
#pragma unroll
                        for (int p = 0; p < 2; p++) {
                            ffma2(acc[p][px][0], w2[p], ippk[ky][kx + 2 * px]);
                            ffma2(acc[p][px][1], w2[p], ippk[ky][kx + 2 * px + 1]);
                            ffma2(acc[p][px][2], w2[p], ippk[ky + 1][kx + 2 * px]);
                            ffma2(acc[p][px][3], w2[p], ippk[ky + 1][kx + 2 * px + 1]);
                        }
                    }
                }
        }
    }

#pragma unroll
    for (int p = 0; p < 2; p++) {
        int co = cob0 + cg * 4 + 2 * p;
#pragma unroll
        for (int px = 0; px < 2; px++) {
            int pxp = lpxt * 2 + px;
#pragma unroll
            for (int dy = 0; dy < 2; dy++)
#pragma unroll
                for (int dx = 0; dx < 2; dx++) {
                    float2 v = unpk(acc[p][px][dy * 2 + dx]);
                    size_t a = (((size_t)nimg * CO + co) * 8 + (2 * lpy + dy)) * 8 +
                               (2 * pxp + dx);
                    slice[a] = v.x;
                    slice[a + 64] = v.y;
                }
        }
    }
}

// ---------------------------------------------------------------------------
// Fused conv4 finalize (sum 4 slices, +bias, ReLU, maxpool2) + BN + flatten.
// ---------------------------------------------------------------------------
__global__ void __launch_bounds__(256)
bn_finalize(const float* __restrict__ pre, const float* __restrict__ b4,
            const float* __restrict__ gamma, const float* __restrict__ beta,
            float* __restrict__ feat) {
    constexpr size_t SL = (size_t)B_ * CH_ * 64;
    int c = blockIdx.x, tid = threadIdx.x;
    float bc = b4[c];
    int g0 = tid * 4;
    int n = g0 >> 4;
    float v[4];
#pragma unroll
    for (int j = 0; j < 4; j++) {
        int g = g0 + j;
        int pp = g & 15;
        int py = pp >> 2, px = pp & 3;
        size_t base = (((size_t)n * CH_ + c) * 8 + 2 * py) * 8 + 2 * px;
        float s00 = 0.f, s01 = 0.f, s10 = 0.f, s11 = 0.f;
#pragma unroll
        for (int s = 0; s < 4; s++) {
            float2 r0 = *(const float2*)(pre + s * SL + base);
            float2 r1 = *(const float2*)(pre + s * SL + base + 8);
            s00 += r0.x; s01 += r0.y; s10 += r1.x; s11 += r1.y;
        }
        float m = fmaxf(fmaxf(s00, s01), fmaxf(s10, s11)) + bc;
        v[j] = fmaxf(m, 0.f);
    }
    float s = v[0] + v[1] + v[2] + v[3];
    float q = v[0] * v[0] + v[1] * v[1] + v[2] * v[2] + v[3] * v[3];
#pragma unroll
    for (int off = 16; off; off >>= 1) {
        s += __shfl_xor_sync(0xffffffffu, s, off);
        q += __shfl_xor_sync(0xffffffffu, q, off);
    }
    __shared__ float rs[8], rq[8];
    __shared__ float s_scale, s_shift;
    int w = tid >> 5, lane = tid & 31;
    if (!lane) { rs[w] = s; rq[w] = q; }
    __syncthreads();
    if (tid == 0) {
        float S = 0.f, Q = 0.f;
#pragma unroll
        for (int j = 0; j < 8; j++) { S += rs[j]; Q += rq[j]; }
        float mean = S * (1.f / 1024.f);
        float var  = Q * (1.f / 1024.f) - mean * mean;
        float r = rsqrtf(var + EPS_);
        float gm = gamma[c] * r;
        s_scale = gm;
        s_shift = beta[c] - mean * gm;
    }
    __syncthreads();
    float gm = s_scale, bt = s_shift;
    float4 o = make_float4(v[0] * gm + bt, v[1] * gm + bt,
                           v[2] * gm + bt, v[3] * gm + bt);
    *(float4*)(feat + (size_t)n * 2560 + c * 16 + (g0 & 15)) = o;
}

// ---------------------------------------------------------------------------
// Routed linear: warp per output element.
// ---------------------------------------------------------------------------
template <bool RELU>
__global__ void __launch_bounds__(256)
fc_routed(const float* __restrict__ X, const float* __restrict__ Wb,
          const float* __restrict__ Bb, const int* __restrict__ act,
          float* __restrict__ Y, int IN, int OD) {
    int n = blockIdx.y;
    int w = threadIdx.x >> 5, lane = threadIdx.x & 31;
    int o = blockIdx.x * (blockDim.x >> 5) + w;
    if (o >= OD) return;
    int e = act[n];
    const float* wr = Wb + ((size_t)e * OD + o) * IN;
    const float* xr = X + (size_t)n * IN;
    float s = 0.f;
    for (int i = lane * 4; i < IN; i += 128) {
        float4 a = *(const float4*)(wr + i);
        float4 b = *(const float4*)(xr + i);
        s += a.x * b.x + a.y * b.y + a.z * b.z + a.w * b.w;
    }
#pragma unroll
    for (int off = 16; off; off >>= 1) s += __shfl_xor_sync(0xffffffffu, s, off);
    if (!lane) {
        float v = s + Bb[(size_t)e * OD + o];
        if (RELU) v = fmaxf(v, 0.f);
        Y[(size_t)n * OD + o] = v;
    }
}

// ---------------------------------------------------------------------------
extern "C" void kernel_launch(void* const* d_in, const int* in_sizes, int n_in,
                              void* d_out, int out_size) {
    const float* x   = (const float*)d_in[0];
    const int* a1    = (const int*)d_in[1];
    const int* a2    = (const int*)d_in[2];
    const int* a3    = (const int*)d_in[3];
    const float* W1  = (const float*)d_in[4];
    const float* b1  = (const float*)d_in[5];
    const float* W2  = (const float*)d_in[6];
    const float* b2  = (const float*)d_in[7];
    const float* W3  = (const float*)d_in[8];
    const float* b3  = (const float*)d_in[9];
    const float* W4  = (const float*)d_in[10];
    const float* b4  = (const float*)d_in[11];
    const float* gam = (const float*)d_in[12];
    const float* bet = (const float*)d_in[13];
    const float* E1W = (const float*)d_in[14];
    const float* E1b = (const float*)d_in[15];
    const float* E2W = (const float*)d_in[16];
    const float* E2b = (const float*)d_in[17];
    const float* E3W = (const float*)d_in[18];
    const float* E3b = (const float*)d_in[19];
    float* out = (float*)d_out;

    float *y1, *y2, *y3, *pre4, *feat, *h1, *h2;
    cudaGetSymbolAddress((void**)&y1, g_y1);
    cudaGetSymbolAddress((void**)&y2, g_y2);
    cudaGetSymbolAddress((void**)&y3, g_y3);
    cudaGetSymbolAddress((void**)&pre4, g_pre4);
    cudaGetSymbolAddress((void**)&feat, g_feat);
    cudaGetSymbolAddress((void**)&h1, g_h1);
    cudaGetSymbolAddress((void**)&h2, g_h2);

    // conv1: 3->160, 64x64 -> 32x32. THP=4,TWPT=8,PX=2,CG=4,CO_T=8,CICH=3.
    conv_pool<3, 64, 64, 4, 8, 2, 4, 8, 3>
        <<<dim3(16, 5, 64), 128>>>(x, W1, b1, y1);
    // conv2: 160->160, 32x32 -> 16x16 (dominant). THP=4,TWPT=8,PX=2,CG=4,CO_T=8.
    conv_pool<160, 32, 32, 4, 8, 2, 4, 8, 8>
        <<<dim3(4, 5, 64), 128>>>(y1, W2, b2, y2);
    // conv3: 160->160, 16x16 -> 8x8. THP=8,TWPT=4,PX=2,CG=8,CO_T=4,CICH=16.
    conv_pool<160, 16, 16, 8, 4, 2, 8, 4, 16>
        <<<dim3(1, 5, 64), 256>>>(y2, W3, b3, y3);
    // conv4 partials: CI split x4.
    conv4_part<<<dim3(4, 5, 64), 64>>>(y3, W4, pre4);
    bn_finalize<<<160, 256>>>(pre4, b4, gam, bet, feat);

    fc_routed<true ><<<dim3(40, 64), 256>>>(feat, E1W, E1b, a1, h1, 2560, 320);
    fc_routed<true ><<<dim3(40, 64), 256>>>(h1,   E2W, E2b, a2, h2, 320, 320);
    fc_routed<false><<<dim3(2, 64),  256>>>(h2,   E3W, E3b, a3, out, 320, 10);
}

// round 9
// speedup vs baseline: 1.5328x; 1.4238x over previous
#include <cuda_runtime.h>
#include <cuda_bf16.h>
#include <cstdint>
#include <cstddef>

// ---------------------------------------------------------------------------
// RoutedAllFC round 9: conv2/conv3 on tensor cores (mma.sync m16n8k16 bf16,
// 3-product hi/lo split ~ fp32 accuracy). Conv = 9 tap-shifted GEMMs over
// K=CI with channel-last bf16 activations (no im2col). conv1/conv4 scalar.
// ---------------------------------------------------------------------------

#define B_   64
#define CH_  160
#define EPS_ 1e-5f

// activations, channel-last bf16 hi/lo splits
__device__ __nv_bfloat16 g_y1h[B_ * 32 * 32 * CH_];
__device__ __nv_bfloat16 g_y1l[B_ * 32 * 32 * CH_];
__device__ __nv_bfloat16 g_y2h[B_ * 16 * 16 * CH_];
__device__ __nv_bfloat16 g_y2l[B_ * 16 * 16 * CH_];
// weights pre-split to bf16 hi/lo in [tap][co][ci]
__device__ __nv_bfloat16 g_w2h[9 * CH_ * CH_];
__device__ __nv_bfloat16 g_w2l[9 * CH_ * CH_];
__device__ __nv_bfloat16 g_w3h[9 * CH_ * CH_];
__device__ __nv_bfloat16 g_w3l[9 * CH_ * CH_];
// fp32 channel-first tail
__device__ float g_y3[B_ * CH_ * 8 * 8];
__device__ float g_pre4[4][B_ * CH_ * 8 * 8];
__device__ float g_feat[B_ * 2560];
__device__ float g_h1[B_ * 320];
__device__ float g_h2[B_ * 320];

// ---- packed f32x2 helpers (scalar conv path) -------------------------------
__device__ __forceinline__ unsigned long long pk2(float x) {
    unsigned long long r;
    asm("mov.b64 %0, {%1, %1};" : "=l"(r) : "f"(x));
    return r;
}
__device__ __forceinline__ void ffma2(unsigned long long& d,
                                      unsigned long long a,
                                      unsigned long long b) {
    asm("fma.rn.f32x2 %0, %1, %2, %3;" : "=l"(d) : "l"(a), "l"(b), "l"(d));
}
__device__ __forceinline__ float2 unpk(unsigned long long v) {
    float2 f;
    asm("mov.b64 {%0, %1}, %2;" : "=f"(f.x), "=f"(f.y) : "l"(v));
    return f;
}

// ---- bf16 split helpers ------------------------------------------------------
__device__ __forceinline__ void bsplit(float v, __nv_bfloat16& h, __nv_bfloat16& l) {
    h = __float2bfloat16(v);
    l = __float2bfloat16(v - __bfloat162float(h));
}

// ---- mma.sync m16n8k16 bf16 -------------------------------------------------
__device__ __forceinline__ void mma16816(float* c, unsigned a0, unsigned a1,
                                         unsigned a2, unsigned a3,
                                         unsigned b0, unsigned b1) {
    asm("mma.sync.aligned.m16n8k16.row.col.f32.bf16.bf16.f32 "
        "{%0,%1,%2,%3},{%4,%5,%6,%7},{%8,%9},{%0,%1,%2,%3};"
        : "+f"(c[0]), "+f"(c[1]), "+f"(c[2]), "+f"(c[3])
        : "r"(a0), "r"(a1), "r"(a2), "r"(a3), "r"(b0), "r"(b1));
}
__device__ __forceinline__ unsigned lds_u32(const __nv_bfloat16* p) {
    return *reinterpret_cast<const unsigned*>(p);
}

// ---------------------------------------------------------------------------
// weight pre-split: W fp32 [co][ci][tap] -> Wh/Wl bf16 [tap][co][ci]
// ---------------------------------------------------------------------------
__global__ void __launch_bounds__(256)
presplit_w(const float* __restrict__ W, __nv_bfloat16* __restrict__ Wh,
           __nv_bfloat16* __restrict__ Wl) {
    int idx = blockIdx.x * 256 + threadIdx.x;
    if (idx >= 9 * CH_ * CH_) return;
    int tap = idx / (CH_ * CH_);
    int r = idx - tap * (CH_ * CH_);
    int co = r / CH_, ci = r - co * CH_;
    float w = W[(co * CH_ + ci) * 9 + tap];
    __nv_bfloat16 h, l;
    bsplit(w, h, l);
    Wh[idx] = h;
    Wl[idx] = l;
}

// ---------------------------------------------------------------------------
// conv1 (scalar): 3->160, 64x64 -> pooled 32x32, output channel-last bf16
// hi/lo. Config: THP=4,TWPT=8,PX=2,CG=4,CO_T=8,CICH=3, 128 thr, grid(16,5,64).
// ---------------------------------------------------------------------------
__global__ void __launch_bounds__(128)
conv1_cl(const float* __restrict__ in, const float* __restrict__ Wt,
         const float* __restrict__ bias,
         __nv_bfloat16* __restrict__ Oh, __nv_bfloat16* __restrict__ Ol) {
    constexpr int CI = 3, HIN = 64, WIN = 64, CO = 160;
    constexpr int THP = 4, TWPT = 8, PX = 2, CG = 4, CO_T = 8, CICH = 3;
    constexpr int TWP = TWPT * PX, TH = 2 * THP, TW = 2 * TWP;
    constexpr int SH = TH + 2, SWD = TW + 2;       // 10 x 34
    constexpr int T = 128, CO_BLK = CG * CO_T, NP = CO_T / 2;
    constexpr int WP = 32;

    __shared__ float s_in[CICH][SH][SWD];
    __shared__ float s_w[CICH][9][CO_BLK];

    const int tid = threadIdx.x;
    const int cg = tid / 32, pix = tid % 32;
    const int lpy = pix / TWPT, lpxt = pix % TWPT;
    const int nimg = blockIdx.z;
    const int cob0 = blockIdx.y * CO_BLK;
    constexpr int TILESX = WP / TWP;               // 2
    const int tpy0 = (blockIdx.x / TILESX) * THP;
    const int tpx0 = (blockIdx.x % TILESX) * TWP;
    const int iy0 = 2 * tpy0 - 1, ix0 = 2 * tpx0 - 1;

    unsigned long long acc[NP][PX][4];
#pragma unroll
    for (int p = 0; p < NP; p++)
#pragma unroll
        for (int px = 0; px < PX; px++)
#pragma unroll
            for (int q = 0; q < 4; q++) acc[p][px][q] = 0ull;

    for (int idx = tid; idx < CICH * SH * SWD; idx += T) {
        int cl = idx / (SH * SWD);
        int rem = idx - cl * (SH * SWD);
        int iy = rem / SWD, ix = rem - iy * SWD;
        int gy = iy0 + iy, gx = ix0 + ix;
        float v = 0.f;
        if ((unsigned)gy < (unsigned)HIN && (unsigned)gx < (unsigned)WIN)
            v = in[(((size_t)nimg * CI + cl) * HIN + gy) * WIN + gx];
        (&s_in[0][0][0])[idx] = v;
    }
    for (int idx = tid; idx < CICH * 9 * CO_BLK; idx += T) {
        int cl = idx / (9 * CO_BLK);
        int rem = idx - cl * (9 * CO_BLK);
        int k = rem / CO_BLK, col = rem - k * CO_BLK;
        (&s_w[0][0][0])[idx] = Wt[((size_t)(cob0 + col) * CI + cl) * 9 + k];
    }
    __syncthreads();

#pragma unroll
    for (int cl = 0; cl < CICH; cl++) {
        const float* sp = &s_in[cl][2 * lpy][2 * lpxt * PX];
        unsigned long long ippk[4][2 * PX + 2];
#pragma unroll
        for (int r = 0; r < 4; r++)
#pragma unroll
            for (int c = 0; c <= PX; c++) {
                float2 a = *(const float2*)(sp + r * SWD + 2 * c);
                ippk[r][2 * c] = pk2(a.x);
                ippk[r][2 * c + 1] = pk2(a.y);
            }
#pragma unroll
        for (int ky = 0; ky < 3; ky++)
#pragma unroll
            for (int kx = 0; kx < 3; kx++) {
                const float* wp = &s_w[cl][ky * 3 + kx][cg * CO_T];
                unsigned long long w2[NP];
#pragma unroll
                for (int p = 0; p < NP; p++)
                    w2[p] = *(const unsigned long long*)(wp + 2 * p);
#pragma unroll
                for (int px = 0; px < PX; px++)
#pragma unroll
                    for (int p = 0; p < NP; p++) {
                        ffma2(acc[p][px][0], w2[p], ippk[ky][kx + 2 * px]);
                        ffma2(acc[p][px][1], w2[p], ippk[ky][kx + 2 * px + 1]);
                        ffma2(acc[p][px][2], w2[p], ippk[ky + 1][kx + 2 * px]);
                        ffma2(acc[p][px][3], w2[p], ippk[ky + 1][kx + 2 * px + 1]);
                    }
            }
    }

#pragma unroll
    for (int p = 0; p < NP; p++) {
        int co = cob0 + cg * CO_T + 2 * p;
        float b0 = bias[co], b1 = bias[co + 1];
#pragma unroll
        for (int px = 0; px < PX; px++) {
            float2 m0 = unpk(acc[p][px][0]), m1 = unpk(acc[p][px][1]);
            float2 m2 = unpk(acc[p][px][2]), m3 = unpk(acc[p][px][3]);
            float v0 = fmaxf(fmaxf(fmaxf(m0.x, m1.x), fmaxf(m2.x, m3.x)) + b0, 0.f);
            float v1 = fmaxf(fmaxf(fmaxf(m0.y, m1.y), fmaxf(m2.y, m3.y)) + b1, 0.f);
            int Y = tpy0 + lpy, X = tpx0 + lpxt * PX + px;
            size_t a = (((size_t)nimg * 32 + Y) * 32 + X) * CH_ + co;
            __nv_bfloat16 h0, l0, h1, l1;
            bsplit(v0, h0, l0);
            bsplit(v1, h1, l1);
            *(__nv_bfloat162*)(Oh + a) = __nv_bfloat162(h0, h1);
            *(__nv_bfloat162*)(Ol + a) = __nv_bfloat162(l0, l1);
        }
    }
}

// ---------------------------------------------------------------------------
// Tensor-core conv3x3(pad1)+bias+ReLU+maxpool2 as 9 tap-shifted GEMMs.
// PP = pre-pool spatial size (input is PP x PP x 160 channel-last bf16 hi/lo).
// Block: 128 thr = 4 warps; tile = 8x8 pre-pool px (M=64, m16/warp), n32.
// K loop: 10 chunks of 16 ci. 3 mmas per (tap, n8): Ah*Wh + Ah*Wl + Al*Wh.
// OUT_CL: write pooled output channel-last bf16 hi/lo; else fp32 chan-first.
// ---------------------------------------------------------------------------
template <int PP, bool OUT_CL>
__global__ void __launch_bounds__(128)
conv_mma(const __nv_bfloat16* __restrict__ Ah, const __nv_bfloat16* __restrict__ Al,
         const __nv_bfloat16* __restrict__ Wh, const __nv_bfloat16* __restrict__ Wl,
         const float* __restrict__ bias,
         __nv_bfloat16* __restrict__ Oh, __nv_bfloat16* __restrict__ Ol,
         float* __restrict__ Ocf) {
    constexpr int CIC = 16;          // ci per chunk
    constexpr int NCH = CH_ / CIC;   // 10 chunks
    constexpr int PPo = PP / 2;      // pooled size
    constexpr int TX = PP / 8;       // tiles per row

    __shared__ alignas(16) __nv_bfloat16 s_ah[10][10][CIC];
    __shared__ alignas(16) __nv_bfloat16 s_al[10][10][CIC];
    __shared__ alignas(16) __nv_bfloat16 s_wh[9][32][CIC];
    __shared__ alignas(16) __nv_bfloat16 s_wl[9][32][CIC];

    const int tid = threadIdx.x;
    const int wrp = tid >> 5, lane = tid & 31;
    const int nimg = blockIdx.z;
    const int nb0 = blockIdx.y * 32;
    const int ty = blockIdx.x / TX, tx = blockIdx.x % TX;
    const int py0 = ty * 8, px0 = tx * 8;

    const int r1 = lane >> 2;        // A row / pre-pool x / B col
    const int kb = (lane & 3) * 2;   // k base within k8
    const int ylo = 2 * wrp, yhi = 2 * wrp + 1;

    float acc[4][4];
#pragma unroll
    for (int f = 0; f < 4; f++)
#pragma unroll
        for (int q = 0; q < 4; q++) acc[f][q] = 0.f;

    for (int cc = 0; cc < NCH; cc++) {
        __syncthreads();
        // stage input tile (10x10 halo, CIC channels, hi+lo), zero-padded
        for (int idx = tid; idx < 400; idx += 128) {
            int p = idx >> 2, q = idx & 3;
            int ly = p / 10, lx = p - ly * 10;
            int gy = py0 - 1 + ly, gx = px0 - 1 + lx;
            uint2 vh = make_uint2(0u, 0u), vl = make_uint2(0u, 0u);
            if ((unsigned)gy < (unsigned)PP && (unsigned)gx < (unsigned)PP) {
                size_t g = (((size_t)nimg * PP + gy) * PP + gx) * CH_ +
                           cc * CIC + q * 4;
                vh = *(const uint2*)(Ah + g);
                vl = *(const uint2*)(Al + g);
            }
            *(uint2*)&s_ah[ly][lx][q * 4] = vh;
            *(uint2*)&s_al[ly][lx][q * 4] = vl;
        }
        // stage weights [tap][n32][CIC] hi+lo
        for (int idx = tid; idx < 1152; idx += 128) {
            int tap = idx >> 7, rem = idx & 127;
            int nn = rem >> 2, q = rem & 3;
            size_t g = ((size_t)tap * CH_ + nb0 + nn) * CH_ + cc * CIC + q * 4;
            *(uint2*)&s_wh[tap][nn][q * 4] = *(const uint2*)(Wh + g);
            *(uint2*)&s_wl[tap][nn][q * 4] = *(const uint2*)(Wl + g);
        }
        __syncthreads();

#pragma unroll
        for (int tap = 0; tap < 9; tap++) {
            const int ky = tap / 3, kx = tap % 3;
            unsigned ah0 = lds_u32(&s_ah[ylo + ky][r1 + kx][kb]);
            unsigned ah1 = lds_u32(&s_ah[yhi + ky][r1 + kx][kb]);
            unsigned ah2 = lds_u32(&s_ah[ylo + ky][r1 + kx][kb + 8]);
            unsigned ah3 = lds_u32(&s_ah[yhi + ky][r1 + kx][kb + 8]);
            unsigned al0 = lds_u32(&s_al[ylo + ky][r1 + kx][kb]);
            unsigned al1 = lds_u32(&s_al[yhi + ky][r1 + kx][kb]);
            unsigned al2 = lds_u32(&s_al[ylo + ky][r1 + kx][kb + 8]);
            unsigned al3 = lds_u32(&s_al[yhi + ky][r1 + kx][kb + 8]);
#pragma unroll
            for (int f = 0; f < 4; f++) {
                int nn = f * 8 + r1;
                unsigned bh0 = lds_u32(&s_wh[tap][nn][kb]);
                unsigned bh1 = lds_u32(&s_wh[tap][nn][kb + 8]);
                unsigned bl0 = lds_u32(&s_wl[tap][nn][kb]);
                unsigned bl1 = lds_u32(&s_wl[tap][nn][kb + 8]);
                mma16816(acc[f], ah0, ah1, ah2, ah3, bh0, bh1);
                mma16816(acc[f], ah0, ah1, ah2, ah3, bl0, bl1);
                mma16816(acc[f], al0, al1, al2, al3, bh0, bh1);
            }
        }
    }

    // epilogue: pool (vertical in-thread, horizontal via shfl), bias, relu
    const int Py = py0 / 2 + wrp;
    const int Px = px0 / 2 + (r1 >> 1);
    const bool writer = ((r1 & 1) == 0);
#pragma unroll
    for (int f = 0; f < 4; f++) {
        int ch = nb0 + f * 8 + kb;
        float v0 = fmaxf(acc[f][0], acc[f][2]);   // cols ch
        float v1 = fmaxf(acc[f][1], acc[f][3]);   // cols ch+1
        float o0 = fmaxf(v0, __shfl_xor_sync(0xffffffffu, v0, 4));
        float o1 = fmaxf(v1, __shfl_xor_sync(0xffffffffu, v1, 4));
        if (writer) {
            o0 = fmaxf(o0 + bias[ch], 0.f);
            o1 = fmaxf(o1 + bias[ch + 1], 0.f);
            if (OUT_CL) {
                size_t a = (((size_t)nimg * PPo + Py) * PPo + Px) * CH_ + ch;
                __nv_bfloat16 h0, l0, h1, l1;
                bsplit(o0, h0, l0);
                bsplit(o1, h1, l1);
                *(__nv_bfloat162*)(Oh + a) = __nv_bfloat162(h0, h1);
                *(__nv_bfloat162*)(Ol + a) = __nv_bfloat162(l0, l1);
            } else {
                size_t a = (((size_t)nimg * CH_ + ch) * PPo + Py) * PPo + Px;
                Ocf[a] = o0;
                Ocf[a + (size_t)PPo * PPo] = o1;
            }
        }
    }
}

// ---------------------------------------------------------------------------
// conv4 partial (scalar, unchanged): CI split x4 into pre-pool partial sums.
// ---------------------------------------------------------------------------
__global__ void __launch_bounds__(64)
conv4_part(const float* __restrict__ in, const float* __restrict__ Wt,
           float* __restrict__ pre) {
    constexpr int CI = 160, CIS = 40, CICH = 8, CO = 160, CO_BLK = 32;
    constexpr int SWD = 10;
    __shared__ float s_in[CICH][10][SWD];
    __shared__ float s_w[CICH][9][CO_BLK];

    const int tid = threadIdx.x;
    const int cg = tid >> 3;
    const int pixt = tid & 7;
    const int lpy = pixt >> 1, lpxt = pixt & 1;
    const int ci0 = blockIdx.x * CIS;
    const int cob0 = blockIdx.y * CO_BLK;
    const int nimg = blockIdx.z;
    float* slice = pre + (size_t)blockIdx.x * (B_ * CH_ * 64);

    unsigned long long acc[2][2][4];
#pragma unroll
    for (int p = 0; p < 2; p++)
#pragma unroll
        for (int px = 0; px < 2; px++)
#pragma unroll
            for (int q = 0; q < 4; q++) acc[p][px][q] = 0ull;

    for (int cc = 0; cc < CIS; cc += CICH) {
        __syncthreads();
        for (int idx = tid; idx < CICH * 10 * SWD; idx += 64) {
            int cl = idx / (10 * SWD), rem = idx - cl * (10 * SWD);
            int iy = rem / SWD, ix = rem - iy * SWD;
            int gy = iy - 1, gx = ix - 1;
            float v = 0.f;
            if ((unsigned)gy < 8u && (unsigned)gx < 8u)
                v = in[(((size_t)nimg * CI + (ci0 + cc + cl)) * 8 + gy) * 8 + gx];
            (&s_in[0][0][0])[idx] = v;
        }
        for (int idx = tid; idx < CICH * 9 * CO_BLK; idx += 64) {
            int cl = idx / (9 * CO_BLK);
            int rem = idx - cl * (9 * CO_BLK);
            int k = rem / CO_BLK, col = rem - k * CO_BLK;
            (&s_w[0][0][0])[idx] =
                Wt[((size_t)(cob0 + col) * CI + (ci0 + cc + cl)) * 9 + k];
        }
        __syncthreads();

#pragma unroll
        for (int cl = 0; cl < CICH; cl++) {
            const float* sp = &s_in[cl][2 * lpy][4 * lpxt];
            unsigned long long ippk[4][6];
#pragma unroll
            for (int r = 0; r < 4; r++)
#pragma unroll
                for (int c = 0; c < 3; c++) {
                    float2 a = *(const float2*)(sp + r * SWD + 2 * c);
                    ippk[r][2 * c] = pk2(a.x);
                    ippk[r][2 * c + 1] = pk2(a.y);
                }
#pragma unroll
            for (int ky = 0; ky < 3; ky++)
#pragma unroll
                for (int kx = 0; kx < 3; kx++) {
                    const float* wp = &s_w[cl][ky * 3 + kx][cg * 4];
                    unsigned long long w2[2];
                    w2[0] = *(const unsigned long long*)(wp);
                    w2[1] = *(const unsigned long long*)(wp + 2);
#pragma unroll
                    for (int px = 0; px < 2; px++)
#pragma unroll
                        for (int p = 0; p < 2; p++) {
                            ffma2(acc[p][px][0], w2[p], ippk[ky][kx + 2 * px]);
                            ffma2(acc[p][px][1], w2[p], ippk[ky][kx + 2 * px + 1]);
                            ffma2(acc[p][px][2], w2[p], ippk[ky + 1][kx + 2 * px]);
                            ffma2(acc[p][px][3], w2[p], ippk[ky + 1][kx + 2 * px + 1]);
                        }
                }
        }
    }

#pragma unroll
    for (int p = 0; p < 2; p++) {
        int co = cob0 + cg * 4 + 2 * p;
#pragma unroll
        for (int px = 0; px < 2; px++) {
            int pxp = lpxt * 2 + px;
#pragma unroll
            for (int dy = 0; dy < 2; dy++)
#pragma unroll
                for (int dx = 0; dx < 2; dx++) {
                    float2 v = unpk(acc[p][px][dy * 2 + dx]);
                    size_t a = (((size_t)nimg * CO + co) * 8 + (2 * lpy + dy)) * 8 +
                               (2 * pxp + dx);
                    slice[a] = v.x;
                    slice[a + 64] = v.y;
                }
        }
    }
}

// ---------------------------------------------------------------------------
// conv4 finalize + BN + flatten (unchanged).
// ---------------------------------------------------------------------------
__global__ void __launch_bounds__(256)
bn_finalize(const float* __restrict__ pre, const float* __restrict__ b4,
            const float* __restrict__ gamma, const float* __restrict__ beta,
            float* __restrict__ feat) {
    constexpr size_t SL = (size_t)B_ * CH_ * 64;
    int c = blockIdx.x, tid = threadIdx.x;
    float bc = b4[c];
    int g0 = tid * 4;
    int n = g0 >> 4;
    float v[4];
#pragma unroll
    for (int j = 0; j < 4; j++) {
        int g = g0 + j;
        int pp = g & 15;
        int py = pp >> 2, px = pp & 3;
        size_t base = (((size_t)n * CH_ + c) * 8 + 2 * py) * 8 + 2 * px;
        float s00 = 0.f, s01 = 0.f, s10 = 0.f, s11 = 0.f;
#pragma unroll
        for (int s = 0; s < 4; s++) {
            float2 r0 = *(const float2*)(pre + s * SL + base);
            float2 r1 = *(const float2*)(pre + s * SL + base + 8);
            s00 += r0.x; s01 += r0.y; s10 += r1.x; s11 += r1.y;
        }
        float m = fmaxf(fmaxf(s00, s01), fmaxf(s10, s11)) + bc;
        v[j] = fmaxf(m, 0.f);
    }
    float s = v[0] + v[1] + v[2] + v[3];
    float q = v[0] * v[0] + v[1] * v[1] + v[2] * v[2] + v[3] * v[3];
#pragma unroll
    for (int off = 16; off; off >>= 1) {
        s += __shfl_xor_sync(0xffffffffu, s, off);
        q += __shfl_xor_sync(0xffffffffu, q, off);
    }
    __shared__ float rs[8], rq[8];
    __shared__ float s_scale, s_shift;
    int w = tid >> 5, lane = tid & 31;
    if (!lane) { rs[w] = s; rq[w] = q; }
    __syncthreads();
    if (tid == 0) {
        float S = 0.f, Q = 0.f;
#pragma unroll
        for (int j = 0; j < 8; j++) { S += rs[j]; Q += rq[j]; }
        float mean = S * (1.f / 1024.f);
        float var = Q * (1.f / 1024.f) - mean * mean;
        float r = rsqrtf(var + EPS_);
        float gm = gamma[c] * r;
        s_scale = gm;
        s_shift = beta[c] - mean * gm;
    }
    __syncthreads();
    float gm = s_scale, bt = s_shift;
    float4 o = make_float4(v[0] * gm + bt, v[1] * gm + bt,
                           v[2] * gm + bt, v[3] * gm + bt);
    *(float4*)(feat + (size_t)n * 2560 + c * 16 + (g0 & 15)) = o;
}

// ---------------------------------------------------------------------------
// Routed linear (unchanged).
// ---------------------------------------------------------------------------
template <bool RELU>
__global__ void __launch_bounds__(256)
fc_routed(const float* __restrict__ X, const float* __restrict__ Wb,
          const float* __restrict__ Bb, const int* __restrict__ act,
          float* __restrict__ Y, int IN, int OD) {
    int n = blockIdx.y;
    int w = threadIdx.x >> 5, lane = threadIdx.x & 31;
    int o = blockIdx.x * (blockDim.x >> 5) + w;
    if (o >= OD) return;
    int e = act[n];
    const float* wr = Wb + ((size_t)e * OD + o) * IN;
    const float* xr = X + (size_t)n * IN;
    float s = 0.f;
    for (int i = lane * 4; i < IN; i += 128) {
        float4 a = *(const float4*)(wr + i);
        float4 b = *(const float4*)(xr + i);
        s += a.x * b.x + a.y * b.y + a.z * b.z + a.w * b.w;
    }
#pragma unroll
    for (int off = 16; off; off >>= 1) s += __shfl_xor_sync(0xffffffffu, s, off);
    if (!lane) {
        float v = s + Bb[(size_t)e * OD + o];
        if (RELU) v = fmaxf(v, 0.f);
        Y[(size_t)n * OD + o] = v;
    }
}

// ---------------------------------------------------------------------------
extern "C" void kernel_launch(void* const* d_in, const int* in_sizes, int n_in,
                              void* d_out, int out_size) {
    const float* x   = (const float*)d_in[0];
    const int* a1    = (const int*)d_in[1];
    const int* a2    = (const int*)d_in[2];
    const int* a3    = (const int*)d_in[3];
    const float* W1  = (const float*)d_in[4];
    const float* b1  = (const float*)d_in[5];
    const float* W2  = (const float*)d_in[6];
    const float* b2  = (const float*)d_in[7];
    const float* W3  = (const float*)d_in[8];
    const float* b3  = (const float*)d_in[9];
    const float* W4  = (const float*)d_in[10];
    const float* b4  = (const float*)d_in[11];
    const float* gam = (const float*)d_in[12];
    const float* bet = (const float*)d_in[13];
    const float* E1W = (const float*)d_in[14];
    const float* E1b = (const float*)d_in[15];
    const float* E2W = (const float*)d_in[16];
    const float* E2b = (const float*)d_in[17];
    const float* E3W = (const float*)d_in[18];
    const float* E3b = (const float*)d_in[19];
    float* out = (float*)d_out;

    __nv_bfloat16 *y1h, *y1l, *y2h, *y2l, *w2h, *w2l, *w3h, *w3l;
    float *y3, *pre4, *feat, *h1, *h2;
    cudaGetSymbolAddress((void**)&y1h, g_y1h);
    cudaGetSymbolAddress((void**)&y1l, g_y1l);
    cudaGetSymbolAddress((void**)&y2h, g_y2h);
    cudaGetSymbolAddress((void**)&y2l, g_y2l);
    cudaGetSymbolAddress((void**)&w2h, g_w2h);
    cudaGetSymbolAddress((void**)&w2l, g_w2l);
    cudaGetSymbolAddress((void**)&w3h, g_w3h);
    cudaGetSymbolAddress((void**)&w3l, g_w3l);
    cudaGetSymbolAddress((void**)&y3, g_y3);
    cudaGetSymbolAddress((void**)&pre4, g_pre4);
    cudaGetSymbolAddress((void**)&feat, g_feat);
    cudaGetSymbolAddress((void**)&h1, g_h1);
    cudaGetSymbolAddress((void**)&h2, g_h2);

    // weight pre-split for tensor-core convs
    int nsplit = (9 * CH_ * CH_ + 255) / 256;
    presplit_w<<<nsplit, 256>>>(W2, w2h, w2l);
    presplit_w<<<nsplit, 256>>>(W3, w3h, w3l);

    // conv1 scalar -> channel-last bf16 hi/lo
    conv1_cl<<<dim3(16, 5, 64), 128>>>(x, W1, b1, y1h, y1l);
    // conv2 tensor: 32x32 prepool -> pooled 16x16, CL bf16 out
    conv_mma<32, true><<<dim3(16, 5, 64), 128>>>(
        y1h, y1l, w2h, w2l, b2, y2h, y2l, nullptr);
    // conv3 tensor: 16x16 prepool -> pooled 8x8, fp32 channel-first out
    conv_mma<16, false><<<dim3(4, 5, 64), 128>>>(
        y2h, y2l, w3h, w3l, b3, nullptr, nullptr, y3);
    // conv4 scalar partials + BN finalize
    conv4_part<<<dim3(4, 5, 64), 64>>>(y3, W4, pre4);
    bn_finalize<<<160, 256>>>(pre4, b4, gam, bet, feat);

    fc_routed<true ><<<dim3(40, 64), 256>>>(feat, E1W, E1b, a1, h1, 2560, 320);
    fc_routed<true ><<<dim3(40, 64), 256>>>(h1,   E2W, E2b, a2, h2, 320, 320);
    fc_routed<false><<<dim3(2, 64),  256>>>(h2,   E3W, E3b, a3, out, 320, 10);
}

// round 10
// speedup vs baseline: 2.0938x; 1.3660x over previous
#include <cuda_runtime.h>
#include <cuda_bf16.h>
#include <cstdint>
#include <cstddef>

// ---------------------------------------------------------------------------
// RoutedAllFC round 10: conv2/conv3/conv4 on tensor cores via one template
// (mma.sync m16n8k16 bf16, 3-product hi/lo split). Fragment loads via
// ldmatrix.x4 from conflict-free padded smem (k-dim 40). CIC=32 (5 chunks).
// ---------------------------------------------------------------------------

#define B_   64
#define CH_  160
#define EPS_ 1e-5f

// activations, channel-last bf16 hi/lo splits
__device__ __nv_bfloat16 g_y1h[B_ * 32 * 32 * CH_];
__device__ __nv_bfloat16 g_y1l[B_ * 32 * 32 * CH_];
__device__ __nv_bfloat16 g_y2h[B_ * 16 * 16 * CH_];
__device__ __nv_bfloat16 g_y2l[B_ * 16 * 16 * CH_];
__device__ __nv_bfloat16 g_y3h[B_ * 8 * 8 * CH_];
__device__ __nv_bfloat16 g_y3l[B_ * 8 * 8 * CH_];
// weights pre-split to bf16 hi/lo in [tap][co][ci]
__device__ __nv_bfloat16 g_w2h[9 * CH_ * CH_];
__device__ __nv_bfloat16 g_w2l[9 * CH_ * CH_];
__device__ __nv_bfloat16 g_w3h[9 * CH_ * CH_];
__device__ __nv_bfloat16 g_w3l[9 * CH_ * CH_];
__device__ __nv_bfloat16 g_w4h[9 * CH_ * CH_];
__device__ __nv_bfloat16 g_w4l[9 * CH_ * CH_];
// fp32 tail
__device__ float g_y4[B_ * CH_ * 4 * 4];
__device__ float g_feat[B_ * 2560];
__device__ float g_h1[B_ * 320];
__device__ float g_h2[B_ * 320];

// ---- packed f32x2 helpers (conv1 scalar path) -------------------------------
__device__ __forceinline__ unsigned long long pk2(float x) {
    unsigned long long r;
    asm("mov.b64 %0, {%1, %1};" : "=l"(r) : "f"(x));
    return r;
}
__device__ __forceinline__ void ffma2(unsigned long long& d,
                                      unsigned long long a,
                                      unsigned long long b) {
    asm("fma.rn.f32x2 %0, %1, %2, %3;" : "=l"(d) : "l"(a), "l"(b), "l"(d));
}
__device__ __forceinline__ float2 unpk(unsigned long long v) {
    float2 f;
    asm("mov.b64 {%0, %1}, %2;" : "=f"(f.x), "=f"(f.y) : "l"(v));
    return f;
}

// ---- bf16 split -------------------------------------------------------------
__device__ __forceinline__ void bsplit(float v, __nv_bfloat16& h, __nv_bfloat16& l) {
    h = __float2bfloat16(v);
    l = __float2bfloat16(v - __bfloat162float(h));
}

// ---- mma + ldmatrix ----------------------------------------------------------
__device__ __forceinline__ void mma16816(float* c, const unsigned* a,
                                         unsigned b0, unsigned b1) {
    asm("mma.sync.aligned.m16n8k16.row.col.f32.bf16.bf16.f32 "
        "{%0,%1,%2,%3},{%4,%5,%6,%7},{%8,%9},{%0,%1,%2,%3};"
        : "+f"(c[0]), "+f"(c[1]), "+f"(c[2]), "+f"(c[3])
        : "r"(a[0]), "r"(a[1]), "r"(a[2]), "r"(a[3]), "r"(b0), "r"(b1));
}
__device__ __forceinline__ void ldsm4(unsigned* r, unsigned addr) {
    asm volatile("ldmatrix.sync.aligned.m8n8.x4.shared.b16 {%0,%1,%2,%3}, [%4];"
                 : "=r"(r[0]), "=r"(r[1]), "=r"(r[2]), "=r"(r[3]) : "r"(addr));
}
__device__ __forceinline__ unsigned scvta(const void* p) {
    return (unsigned)__cvta_generic_to_shared(p);
}

// ---------------------------------------------------------------------------
// weight pre-split: W fp32 [co][ci][tap] -> Wh/Wl bf16 [tap][co][ci]
// ---------------------------------------------------------------------------
__global__ void __launch_bounds__(256)
presplit_w(const float* __restrict__ W, __nv_bfloat16* __restrict__ Wh,
           __nv_bfloat16* __restrict__ Wl) {
    int idx = blockIdx.x * 256 + threadIdx.x;
    if (idx >= 9 * CH_ * CH_) return;
    int tap = idx / (CH_ * CH_);
    int r = idx - tap * (CH_ * CH_);
    int co = r / CH_, ci = r - co * CH_;
    float w = W[(co * CH_ + ci) * 9 + tap];
    __nv_bfloat16 h, l;
    bsplit(w, h, l);
    Wh[idx] = h;
    Wl[idx] = l;
}

// ---------------------------------------------------------------------------
// conv1 (scalar): 3->160, 64x64 -> pooled 32x32, channel-last bf16 hi/lo out.
// ---------------------------------------------------------------------------
__global__ void __launch_bounds__(128)
conv1_cl(const float* __restrict__ in, const float* __restrict__ Wt,
         const float* __restrict__ bias,
         __nv_bfloat16* __restrict__ Oh, __nv_bfloat16* __restrict__ Ol) {
    constexpr int CI = 3, HIN = 64, WIN = 64;
    constexpr int THP = 4, TWPT = 8, PX = 2, CO_T = 8, CICH = 3;
    constexpr int TWP = TWPT * PX, TH = 2 * THP, TW = 2 * TWP;
    constexpr int SH = TH + 2, SWD = TW + 2;
    constexpr int T = 128, CO_BLK = 32, NP = CO_T / 2;
    constexpr int WP = 32;

    __shared__ float s_in[CICH][SH][SWD];
    __shared__ float s_w[CICH][9][CO_BLK];

    const int tid = threadIdx.x;
    const int cg = tid / 32, pix = tid % 32;
    const int lpy = pix / TWPT, lpxt = pix % TWPT;
    const int nimg = blockIdx.z;
    const int cob0 = blockIdx.y * CO_BLK;
    constexpr int TILESX = WP / TWP;
    const int tpy0 = (blockIdx.x / TILESX) * THP;
    const int tpx0 = (blockIdx.x % TILESX) * TWP;
    const int iy0 = 2 * tpy0 - 1, ix0 = 2 * tpx0 - 1;

    unsigned long long acc[NP][PX][4];
#pragma unroll
    for (int p = 0; p < NP; p++)
#pragma unroll
        for (int px = 0; px < PX; px++)
#pragma unroll
            for (int q = 0; q < 4; q++) acc[p][px][q] = 0ull;

    for (int idx = tid; idx < CICH * SH * SWD; idx += T) {
        int cl = idx / (SH * SWD);
        int rem = idx - cl * (SH * SWD);
        int iy = rem / SWD, ix = rem - iy * SWD;
        int gy = iy0 + iy, gx = ix0 + ix;
        float v = 0.f;
        if ((unsigned)gy < (unsigned)HIN && (unsigned)gx < (unsigned)WIN)
            v = in[(((size_t)nimg * CI + cl) * HIN + gy) * WIN + gx];
        (&s_in[0][0][0])[idx] = v;
    }
    for (int idx = tid; idx < CICH * 9 * CO_BLK; idx += T) {
        int cl = idx / (9 * CO_BLK);
        int rem = idx - cl * (9 * CO_BLK);
        int k = rem / CO_BLK, col = rem - k * CO_BLK;
        (&s_w[0][0][0])[idx] = Wt[((size_t)(cob0 + col) * CI + cl) * 9 + k];
    }
    __syncthreads();

#pragma unroll
    for (int cl = 0; cl < CICH; cl++) {
        const float* sp = &s_in[cl][2 * lpy][2 * lpxt * PX];
        unsigned long long ippk[4][2 * PX + 2];
#pragma unroll
        for (int r = 0; r < 4; r++)
#pragma unroll
            for (int c = 0; c <= PX; c++) {
                float2 a = *(const float2*)(sp + r * SWD + 2 * c);
                ippk[r][2 * c] = pk2(a.x);
                ippk[r][2 * c + 1] = pk2(a.y);
            }
#pragma unroll
        for (int ky = 0; ky < 3; ky++)
#pragma unroll
            for (int kx = 0; kx < 3; kx++) {
                const float* wp = &s_w[cl][ky * 3 + kx][cg * CO_T];
                unsigned long long w2[NP];
#pragma unroll
                for (int p = 0; p < NP; p++)
                    w2[p] = *(const unsigned long long*)(wp + 2 * p);
#pragma unroll
                for (int px = 0; px < PX; px++)
#pragma unroll
                    for (int p = 0; p < NP; p++) {
                        ffma2(acc[p][px][0], w2[p], ippk[ky][kx + 2 * px]);
                        ffma2(acc[p][px][1], w2[p], ippk[ky][kx + 2 * px + 1]);
                        ffma2(acc[p][px][2], w2[p], ippk[ky + 1][kx + 2 * px]);
                        ffma2(acc[p][px][3], w2[p], ippk[ky + 1][kx + 2 * px + 1]);
                    }
            }
    }

#pragma unroll
    for (int p = 0; p < NP; p++) {
        int co = cob0 + cg * CO_T + 2 * p;
        float b0 = bias[co], b1 = bias[co + 1];
#pragma unroll
        for (int px = 0; px < PX; px++) {
            float2 m0 = unpk(acc[p][px][0]), m1 = unpk(acc[p][px][1]);
            float2 m2 = unpk(acc[p][px][2]), m3 = unpk(acc[p][px][3]);
            float v0 = fmaxf(fmaxf(fmaxf(m0.x, m1.x), fmaxf(m2.x, m3.x)) + b0, 0.f);
            float v1 = fmaxf(fmaxf(fmaxf(m0.y, m1.y), fmaxf(m2.y, m3.y)) + b1, 0.f);
            int Y = tpy0 + lpy, X = tpx0 + lpxt * PX + px;
            size_t a = (((size_t)nimg * 32 + Y) * 32 + X) * CH_ + co;
            __nv_bfloat16 h0, l0, h1, l1;
            bsplit(v0, h0, l0);
            bsplit(v1, h1, l1);
            *(__nv_bfloat162*)(Oh + a) = __nv_bfloat162(h0, h1);
            *(__nv_bfloat162*)(Ol + a) = __nv_bfloat162(l0, l1);
        }
    }
}

// ---------------------------------------------------------------------------
// Tensor-core conv3x3(pad1)+bias+ReLU+maxpool2, 9 tap-shifted GEMMs.
// Fragments via ldmatrix.x4 from padded smem (k-stride 40 elems = 80B,
// conflict-free LDSM). CIC=32 (5 chunks). Block = 4 warps, tile 8x8 prepool
// (M=64, m16/warp), N=32 channels. 3 mmas per (tap,f): Ah*Wh + Ah*Wl + Al*Wh.
// ---------------------------------------------------------------------------
template <int PP, bool OUT_CL>
__global__ void __launch_bounds__(128)
conv_mma(const __nv_bfloat16* __restrict__ Ah, const __nv_bfloat16* __restrict__ Al,
         const __nv_bfloat16* __restrict__ Wh, const __nv_bfloat16* __restrict__ Wl,
         const float* __restrict__ bias,
         __nv_bfloat16* __restrict__ Oh, __nv_bfloat16* __restrict__ Ol,
         float* __restrict__ Ocf) {
    constexpr int CIC = 32;          // ci per chunk
    constexpr int KP = 40;           // padded k stride (80B, LDSM conflict-free)
    constexpr int NCH = CH_ / CIC;   // 5 chunks
    constexpr int PPo = PP / 2;
    constexpr int TX = PP / 8;

    __shared__ alignas(16) __nv_bfloat16 s_ah[10][10][KP];
    __shared__ alignas(16) __nv_bfloat16 s_al[10][10][KP];
    __shared__ alignas(16) __nv_bfloat16 s_wh[9][32][KP];
    __shared__ alignas(16) __nv_bfloat16 s_wl[9][32][KP];

    const int tid = threadIdx.x;
    const int wrp = tid >> 5, lane = tid & 31;
    const int nimg = blockIdx.z;
    const int nb0 = blockIdx.y * 32;
    const int ty = blockIdx.x / TX, tx = blockIdx.x % TX;
    const int py0 = ty * 8, px0 = tx * 8;

    const int r1 = lane >> 2;        // C-fragment row (= x) / col group
    const int kb = (lane & 3) * 2;   // C-fragment channel pair base
    // ldmatrix lane roles
    const int seg = lane >> 3, lx8 = lane & 7;
    const int ay = 2 * wrp + (seg & 1);       // A row (y) for this lane's matrix
    const int akoff = (seg >> 1) * 8;         // A k offset within k16
    const int nrow0 = 8 * (seg >> 1) + lx8;   // B n row within f-pair
    const int bk0 = (seg & 1) * 8;            // B k offset within k16

    const unsigned a_h_base = scvta(&s_ah[ay][lx8][akoff]);
    const unsigned a_l_base = scvta(&s_al[ay][lx8][akoff]);
    const unsigned b_h_base = scvta(&s_wh[0][nrow0][bk0]);
    const unsigned b_l_base = scvta(&s_wl[0][nrow0][bk0]);

    float acc[4][4];
#pragma unroll
    for (int f = 0; f < 4; f++)
#pragma unroll
        for (int q = 0; q < 4; q++) acc[f][q] = 0.f;

    for (int cc = 0; cc < NCH; cc++) {
        __syncthreads();
        // stage input tile (10x10 halo, 32 ch, hi+lo), zero-padded, 16B chunks
        for (int idx = tid; idx < 400; idx += 128) {
            int p = idx >> 2, q = idx & 3;
            int ly = p / 10, lx = p - ly * 10;
            int gy = py0 - 1 + ly, gx = px0 - 1 + lx;
            uint4 vh = make_uint4(0u, 0u, 0u, 0u), vl = vh;
            if ((unsigned)gy < (unsigned)PP && (unsigned)gx < (unsigned)PP) {
                size_t g = (((size_t)nimg * PP + gy) * PP + gx) * CH_ +
                           cc * CIC + q * 8;
                vh = *(const uint4*)(Ah + g);
                vl = *(const uint4*)(Al + g);
            }
            *(uint4*)&s_ah[ly][lx][q * 8] = vh;
            *(uint4*)&s_al[ly][lx][q * 8] = vl;
        }
        // stage weights [tap][n32][32] hi+lo
        for (int idx = tid; idx < 1152; idx += 128) {
            int tap = idx >> 7, rem = idx & 127;
            int nn = rem >> 2, q = rem & 3;
            size_t g = ((size_t)tap * CH_ + nb0 + nn) * CH_ + cc * CIC + q * 8;
            *(uint4*)&s_wh[tap][nn][q * 8] = *(const uint4*)(Wh + g);
            *(uint4*)&s_wl[tap][nn][q * 8] = *(const uint4*)(Wl + g);
        }
        __syncthreads();

#pragma unroll
        for (int tap = 0; tap < 9; tap++) {
            const int ky = tap / 3, kx = tap % 3;
#pragma unroll
            for (int ks = 0; ks < 2; ks++) {
                const unsigned aoff = (unsigned)((ky * 10 + kx) * (KP * 2) + ks * 32);
                unsigned ah[4], al[4];
                ldsm4(ah, a_h_base + aoff);
                ldsm4(al, a_l_base + aoff);
#pragma unroll
                for (int fp = 0; fp < 4; fp += 2) {
                    const unsigned boff =
                        (unsigned)(tap * (32 * KP * 2) + fp * (8 * KP * 2) + ks * 32);
                    unsigned bh[4], bl[4];
                    ldsm4(bh, b_h_base + boff);
                    ldsm4(bl, b_l_base + boff);
                    mma16816(acc[fp], ah, bh[0], bh[1]);
                    mma16816(acc[fp], ah, bl[0], bl[1]);
                    mma16816(acc[fp], al, bh[0], bh[1]);
                    mma16816(acc[fp + 1], ah, bh[2], bh[3]);
                    mma16816(acc[fp + 1], ah, bl[2], bl[3]);
                    mma16816(acc[fp + 1], al, bh[2], bh[3]);
                }
            }
        }
    }

    // epilogue: pool (vertical in-thread, horizontal shfl), bias, relu
    const int Py = py0 / 2 + wrp;
    const int Px = px0 / 2 + (r1 >> 1);
    const bool writer = ((r1 & 1) == 0);
#pragma unroll
    for (int f = 0; f < 4; f++) {
        int ch = nb0 + f * 8 + kb;
        float v0 = fmaxf(acc[f][0], acc[f][2]);
        float v1 = fmaxf(acc[f][1], acc[f][3]);
        float o0 = fmaxf(v0, __shfl_xor_sync(0xffffffffu, v0, 4));
        float o1 = fmaxf(v1, __shfl_xor_sync(0xffffffffu, v1, 4));
        if (writer) {
            o0 = fmaxf(o0 + bias[ch], 0.f);
            o1 = fmaxf(o1 + bias[ch + 1], 0.f);
            if (OUT_CL) {
                size_t a = (((size_t)nimg * PPo + Py) * PPo + Px) * CH_ + ch;
                __nv_bfloat16 h0, l0, h1, l1;
                bsplit(o0, h0, l0);
                bsplit(o1, h1, l1);
                *(__nv_bfloat162*)(Oh + a) = __nv_bfloat162(h0, h1);
                *(__nv_bfloat162*)(Ol + a) = __nv_bfloat162(l0, l1);
            } else {
                size_t a = (((size_t)nimg * CH_ + ch) * PPo + Py) * PPo + Px;
                Ocf[a] = o0;
                Ocf[a + (size_t)PPo * PPo] = o1;
            }
        }
    }
}

// ---------------------------------------------------------------------------
// BatchNorm (batch stats) + affine + flatten. One block per channel.
// ---------------------------------------------------------------------------
__global__ void __launch_bounds__(256)
bn_flatten(const float* __restrict__ y4, const float* __restrict__ gamma,
           const float* __restrict__ beta, float* __restrict__ feat) {
    int c = blockIdx.x, tid = threadIdx.x;
    int i0 = tid * 4;
    int n = i0 >> 4, hw = i0 & 15;
    float4 v = *(const float4*)(y4 + (((size_t)n * 160 + c) << 4) + hw);
    float s = v.x + v.y + v.z + v.w;
    float q = v.x * v.x + v.y * v.y + v.z * v.z + v.w * v.w;
#pragma unroll
    for (int off = 16; off; off >>= 1) {
        s += __shfl_xor_sync(0xffffffffu, s, off);
        q += __shfl_xor_sync(0xffffffffu, q, off);
    }
    __shared__ float rs[8], rq[8];
    __shared__ float s_scale, s_shift;
    int w = tid >> 5, lane = tid & 31;
    if (!lane) { rs[w] = s; rq[w] = q; }
    __syncthreads();
    if (tid == 0) {
        float S = 0.f, Q = 0.f;
#pragma unroll
        for (int j = 0; j < 8; j++) { S += rs[j]; Q += rq[j]; }
        float mean = S * (1.f / 1024.f);
        float var = Q * (1.f / 1024.f) - mean * mean;
        float r = rsqrtf(var + EPS_);
        float g = gamma[c] * r;
        s_scale = g;
        s_shift = beta[c] - mean * g;
    }
    __syncthreads();
    float g = s_scale, b = s_shift;
    float4 o = make_float4(v.x * g + b, v.y * g + b, v.z * g + b, v.w * g + b);
    *(float4*)(feat + (size_t)n * 2560 + c * 16 + hw) = o;
}

// ---------------------------------------------------------------------------
// Routed linear: warp per output element.
// ---------------------------------------------------------------------------
template <bool RELU>
__global__ void __launch_bounds__(256)
fc_routed(const float* __restrict__ X, const float* __restrict__ Wb,
          const float* __restrict__ Bb, const int* __restrict__ act,
          float* __restrict__ Y, int IN, int OD) {
    int n = blockIdx.y;
    int w = threadIdx.x >> 5, lane = threadIdx.x & 31;
    int o = blockIdx.x * (blockDim.x >> 5) + w;
    if (o >= OD) return;
    int e = act[n];
    const float* wr = Wb + ((size_t)e * OD + o) * IN;
    const float* xr = X + (size_t)n * IN;
    float s = 0.f;
    for (int i = lane * 4; i < IN; i += 128) {
        float4 a = *(const float4*)(wr + i);
        float4 b = *(const float4*)(xr + i);
        s += a.x * b.x + a.y * b.y + a.z * b.z + a.w * b.w;
    }
#pragma unroll
    for (int off = 16; off; off >>= 1) s += __shfl_xor_sync(0xffffffffu, s, off);
    if (!lane) {
        float v = s + Bb[(size_t)e * OD + o];
        if (RELU) v = fmaxf(v, 0.f);
        Y[(size_t)n * OD + o] = v;
    }
}

// ---------------------------------------------------------------------------
extern "C" void kernel_launch(void* const* d_in, const int* in_sizes, int n_in,
                              void* d_out, int out_size) {
    const float* x   = (const float*)d_in[0];
    const int* a1    = (const int*)d_in[1];
    const int* a2    = (const int*)d_in[2];
    const int* a3    = (const int*)d_in[3];
    const float* W1  = (const float*)d_in[4];
    const float* b1  = (const float*)d_in[5];
    const float* W2  = (const float*)d_in[6];
    const float* b2  = (const float*)d_in[7];
    const float* W3  = (const float*)d_in[8];
    const float* b3  = (const float*)d_in[9];
    const float* W4  = (const float*)d_in[10];
    const float* b4  = (const float*)d_in[11];
    const float* gam = (const float*)d_in[12];
    const float* bet = (const float*)d_in[13];
    const float* E1W = (const float*)d_in[14];
    const float* E1b = (const float*)d_in[15];
    const float* E2W = (const float*)d_in[16];
    const float* E2b = (const float*)d_in[17];
    const float* E3W = (const float*)d_in[18];
    const float* E3b = (const float*)d_in[19];
    float* out = (float*)d_out;

    __nv_bfloat16 *y1h, *y1l, *y2h, *y2l, *y3h, *y3l;
    __nv_bfloat16 *w2h, *w2l, *w3h, *w3l, *w4h, *w4l;
    float *y4, *feat, *h1, *h2;
    cudaGetSymbolAddress((void**)&y1h, g_y1h);
    cudaGetSymbolAddress((void**)&y1l, g_y1l);
    cudaGetSymbolAddress((void**)&y2h, g_y2h);
    cudaGetSymbolAddress((void**)&y2l, g_y2l);
    cudaGetSymbolAddress((void**)&y3h, g_y3h);
    cudaGetSymbolAddress((void**)&y3l, g_y3l);
    cudaGetSymbolAddress((void**)&w2h, g_w2h);
    cudaGetSymbolAddress((void**)&w2l, g_w2l);
    cudaGetSymbolAddress((void**)&w3h, g_w3h);
    cudaGetSymbolAddress((void**)&w3l, g_w3l);
    cudaGetSymbolAddress((void**)&w4h, g_w4h);
    cudaGetSymbolAddress((void**)&w4l, g_w4l);
    cudaGetSymbolAddress((void**)&y4, g_y4);
    cudaGetSymbolAddress((void**)&feat, g_feat);
    cudaGetSymbolAddress((void**)&h1, g_h1);
    cudaGetSymbolAddress((void**)&h2, g_h2);

    // weight pre-split for tensor-core convs
    int nsplit = (9 * CH_ * CH_ + 255) / 256;
    presplit_w<<<nsplit, 256>>>(W2, w2h, w2l);
    presplit_w<<<nsplit, 256>>>(W3, w3h, w3l);
    presplit_w<<<nsplit, 256>>>(W4, w4h, w4l);

    // conv1 scalar -> channel-last bf16 hi/lo
    conv1_cl<<<dim3(16, 5, 64), 128>>>(x, W1, b1, y1h, y1l);
    // conv2 tensor: 32x32 prepool -> 16x16, CL bf16 out
    conv_mma<32, true><<<dim3(16, 5, 64), 128>>>(
        y1h, y1l, w2h, w2l, b2, y2h, y2l, nullptr);
    // conv3 tensor: 16x16 prepool -> 8x8, CL bf16 out
    conv_mma<16, true><<<dim3(4, 5, 64), 128>>>(
        y2h, y2l, w3h, w3l, b3, y3h, y3l, nullptr);
    // conv4 tensor: 8x8 prepool -> 4x4, fp32 channel-first out
    conv_mma<8, false><<<dim3(1, 5, 64), 128>>>(
        y3h, y3l, w4h, w4l, b4, nullptr, nullptr, y4);

    bn_flatten<<<160, 256>>>(y4, gam, bet, feat);

    fc_routed<true ><<<dim3(40, 64), 256>>>(feat, E1W, E1b, a1, h1, 2560, 320);
    fc_routed<true ><<<dim3(40, 64), 256>>>(h1,   E2W, E2b, a2, h2, 320, 320);
    fc_routed<false><<<dim3(2, 64),  256>>>(h2,   E3W, E3b, a3, out, 320, 10);
}

// round 11
// speedup vs baseline: 2.1922x; 1.0470x over previous
#include <cuda_runtime.h>
#include <cuda_bf16.h>
#include <cstdint>
#include <cstddef>

// ---------------------------------------------------------------------------
// RoutedAllFC round 11: ALL four convs on tensor cores. conv1 via im2col
// (K=27 padded to 32, single k-chunk GEMM). conv2/3/4 unchanged from r10
// (mma.sync m16n8k16 bf16 3-product hi/lo split, ldmatrix.x4, KP=40).
// ---------------------------------------------------------------------------

#define B_   64
#define CH_  160
#define EPS_ 1e-5f

// activations, channel-last bf16 hi/lo splits
__device__ __nv_bfloat16 g_y1h[B_ * 32 * 32 * CH_];
__device__ __nv_bfloat16 g_y1l[B_ * 32 * 32 * CH_];
__device__ __nv_bfloat16 g_y2h[B_ * 16 * 16 * CH_];
__device__ __nv_bfloat16 g_y2l[B_ * 16 * 16 * CH_];
__device__ __nv_bfloat16 g_y3h[B_ * 8 * 8 * CH_];
__device__ __nv_bfloat16 g_y3l[B_ * 8 * 8 * CH_];
// weights pre-split to bf16 hi/lo
__device__ __nv_bfloat16 g_w1h[CH_ * 32];         // [co][k=ci*9+tap, pad 32]
__device__ __nv_bfloat16 g_w1l[CH_ * 32];
__device__ __nv_bfloat16 g_w2h[9 * CH_ * CH_];    // [tap][co][ci]
__device__ __nv_bfloat16 g_w2l[9 * CH_ * CH_];
__device__ __nv_bfloat16 g_w3h[9 * CH_ * CH_];
__device__ __nv_bfloat16 g_w3l[9 * CH_ * CH_];
__device__ __nv_bfloat16 g_w4h[9 * CH_ * CH_];
__device__ __nv_bfloat16 g_w4l[9 * CH_ * CH_];
// fp32 tail
__device__ float g_y4[B_ * CH_ * 4 * 4];
__device__ float g_feat[B_ * 2560];
__device__ float g_h1[B_ * 320];
__device__ float g_h2[B_ * 320];

// ---- bf16 split -------------------------------------------------------------
__device__ __forceinline__ void bsplit(float v, __nv_bfloat16& h, __nv_bfloat16& l) {
    h = __float2bfloat16(v);
    l = __float2bfloat16(v - __bfloat162float(h));
}

// ---- mma + ldmatrix ----------------------------------------------------------
__device__ __forceinline__ void mma16816(float* c, const unsigned* a,
                                         unsigned b0, unsigned b1) {
    asm("mma.sync.aligned.m16n8k16.row.col.f32.bf16.bf16.f32 "
        "{%0,%1,%2,%3},{%4,%5,%6,%7},{%8,%9},{%0,%1,%2,%3};"
        : "+f"(c[0]), "+f"(c[1]), "+f"(c[2]), "+f"(c[3])
        : "r"(a[0]), "r"(a[1]), "r"(a[2]), "r"(a[3]), "r"(b0), "r"(b1));
}
__device__ __forceinline__ void ldsm4(unsigned* r, unsigned addr) {
    asm volatile("ldmatrix.sync.aligned.m8n8.x4.shared.b16 {%0,%1,%2,%3}, [%4];"
                 : "=r"(r[0]), "=r"(r[1]), "=r"(r[2]), "=r"(r[3]) : "r"(addr));
}
__device__ __forceinline__ unsigned scvta(const void* p) {
    return (unsigned)__cvta_generic_to_shared(p);
}

// ---------------------------------------------------------------------------
// weight pre-splits
// ---------------------------------------------------------------------------
__global__ void __launch_bounds__(256)
presplit_w(const float* __restrict__ W, __nv_bfloat16* __restrict__ Wh,
           __nv_bfloat16* __restrict__ Wl) {
    int idx = blockIdx.x * 256 + threadIdx.x;
    if (idx >= 9 * CH_ * CH_) return;
    int tap = idx / (CH_ * CH_);
    int r = idx - tap * (CH_ * CH_);
    int co = r / CH_, ci = r - co * CH_;
    float w = W[(co * CH_ + ci) * 9 + tap];
    __nv_bfloat16 h, l;
    bsplit(w, h, l);
    Wh[idx] = h;
    Wl[idx] = l;
}

// conv1 weights: fp32 [co][ci][3][3] -> bf16 [co][32] with k = ci*9+tap, pad 0
__global__ void __launch_bounds__(256)
presplit_w1(const float* __restrict__ W, __nv_bfloat16* __restrict__ Wh,
            __nv_bfloat16* __restrict__ Wl) {
    int idx = blockIdx.x * 256 + threadIdx.x;
    if (idx >= CH_ * 32) return;
    int co = idx >> 5, k = idx & 31;
    float w = (k < 27) ? W[co * 27 + k] : 0.f;
    __nv_bfloat16 h, l;
    bsplit(w, h, l);
    Wh[idx] = h;
    Wl[idx] = l;
}

// ---------------------------------------------------------------------------
// conv1 tensor: im2col GEMM. M=64 prepool px (8x8 tile), N=32 co, K=32
// (27 real: 3 ci x 9 taps), single k-chunk. Input fp32 NCHW; output pooled
// 32x32 channel-last bf16 hi/lo.
// ---------------------------------------------------------------------------
__global__ void __launch_bounds__(128)
conv1_mma(const float* __restrict__ x,
          const __nv_bfloat16* __restrict__ Wh, const __nv_bfloat16* __restrict__ Wl,
          const float* __restrict__ bias,
          __nv_bfloat16* __restrict__ Oh, __nv_bfloat16* __restrict__ Ol) {
    constexpr int KP = 40;
    __shared__ float s_halo[3][10][10];
    __shared__ alignas(16) __nv_bfloat16 s_ah[64][KP];
    __shared__ alignas(16) __nv_bfloat16 s_al[64][KP];
    __shared__ alignas(16) __nv_bfloat16 s_wh[32][KP];
    __shared__ alignas(16) __nv_bfloat16 s_wl[32][KP];

    const int tid = threadIdx.x;
    const int wrp = tid >> 5, lane = tid & 31;
    const int nimg = blockIdx.z;
    const int nb0 = blockIdx.y * 32;
    const int ty = blockIdx.x >> 3, tx = blockIdx.x & 7;
    const int py0 = ty * 8, px0 = tx * 8;

    // stage halo 10x10x3 fp32 (zero-padded)
    for (int idx = tid; idx < 300; idx += 128) {
        int ci = idx / 100, rem = idx - ci * 100;
        int ly = rem / 10, lx = rem - ly * 10;
        int gy = py0 - 1 + ly, gx = px0 - 1 + lx;
        float v = 0.f;
        if ((unsigned)gy < 64u && (unsigned)gx < 64u)
            v = x[(((size_t)nimg * 3 + ci) * 64 + gy) * 64 + gx];
        s_halo[ci][ly][lx] = v;
    }
    // stage weights [n32][32] hi+lo
    for (int idx = tid; idx < 1024; idx += 128) {
        int nn = idx >> 5, k = idx & 31;
        s_wh[nn][k] = Wh[(nb0 + nn) * 32 + k];
        s_wl[nn][k] = Wl[(nb0 + nn) * 32 + k];
    }
    __syncthreads();

    // im2col: A[m=py*8+px][k=ci*9+tap], bf16 hi/lo split
    for (int idx = tid; idx < 2048; idx += 128) {
        int m = idx >> 5, k = idx & 31;
        int yy = m >> 3, xx = m & 7;
        float v = 0.f;
        if (k < 27) {
            int ci = k / 9, tap = k - ci * 9;
            int ky = tap / 3, kx = tap - ky * 3;
            v = s_halo[ci][yy + ky][xx + kx];
        }
        __nv_bfloat16 h, l;
        bsplit(v, h, l);
        s_ah[m][k] = h;
        s_al[m][k] = l;
    }
    __syncthreads();

    // fragment roles (identical layout to conv_mma)
    const int r1 = lane >> 2;
    const int kb = (lane & 3) * 2;
    const int seg = lane >> 3, lx8 = lane & 7;
    const unsigned a_h_base = scvta(&s_ah[16 * wrp + (seg & 1) * 8 + lx8][(seg >> 1) * 8]);
    const unsigned a_l_base = scvta(&s_al[16 * wrp + (seg & 1) * 8 + lx8][(seg >> 1) * 8]);
    const int nrow0 = 8 * (seg >> 1) + lx8;
    const int bk0 = (seg & 1) * 8;
    const unsigned b_h_base = scvta(&s_wh[nrow0][bk0]);
    const unsigned b_l_base = scvta(&s_wl[nrow0][bk0]);

    float acc[4][4];
#pragma unroll
    for (int f = 0; f < 4; f++)
#pragma unroll
        for (int q = 0; q < 4; q++) acc[f][q] = 0.f;

#pragma unroll
    for (int ks = 0; ks < 2; ks++) {
        unsigned ah[4], al[4];
        ldsm4(ah, a_h_base + ks * 32);
        ldsm4(al, a_l_base + ks * 32);
#pragma unroll
        for (int fp = 0; fp < 4; fp += 2) {
            const unsigned boff = (unsigned)(fp * (8 * KP * 2) + ks * 32);
            unsigned bh[4], bl[4];
            ldsm4(bh, b_h_base + boff);
            ldsm4(bl, b_l_base + boff);
            mma16816(acc[fp], ah, bh[0], bh[1]);
            mma16816(acc[fp], ah, bl[0], bl[1]);
            mma16816(acc[fp], al, bh[0], bh[1]);
            mma16816(acc[fp + 1], ah, bh[2], bh[3]);
            mma16816(acc[fp + 1], ah, bl[2], bl[3]);
            mma16816(acc[fp + 1], al, bh[2], bh[3]);
        }
    }

    // epilogue: pool + bias + relu, channel-last bf16 hi/lo out (32x32)
    const int Py = py0 / 2 + wrp;
    const int Px = px0 / 2 + (r1 >> 1);
    const bool writer = ((r1 & 1) == 0);
#pragma unroll
    for (int f = 0; f < 4; f++) {
        int ch = nb0 + f * 8 + kb;
        float v0 = fmaxf(acc[f][0], acc[f][2]);
        float v1 = fmaxf(acc[f][1], acc[f][3]);
        float o0 = fmaxf(v0, __shfl_xor_sync(0xffffffffu, v0, 4));
        float o1 = fmaxf(v1, __shfl_xor_sync(0xffffffffu, v1, 4));
        if (writer) {
            o0 = fmaxf(o0 + bias[ch], 0.f);
            o1 = fmaxf(o1 + bias[ch + 1], 0.f);
            size_t a = (((size_t)nimg * 32 + Py) * 32 + Px) * CH_ + ch;
            __nv_bfloat16 h0, l0, h1, l1;
            bsplit(o0, h0, l0);
            bsplit(o1, h1, l1);
            *(__nv_bfloat162*)(Oh + a) = __nv_bfloat162(h0, h1);
            *(__nv_bfloat162*)(Ol + a) = __nv_bfloat162(l0, l1);
        }
    }
}

// ---------------------------------------------------------------------------
// Tensor-core conv3x3(pad1)+bias+ReLU+maxpool2, 9 tap-shifted GEMMs.
// (unchanged from round 10)
// ---------------------------------------------------------------------------
template <int PP, bool OUT_CL>
__global__ void __launch_bounds__(128)
conv_mma(const __nv_bfloat16* __restrict__ Ah, const __nv_bfloat16* __restrict__ Al,
         const __nv_bfloat16* __restrict__ Wh, const __nv_bfloat16* __restrict__ Wl,
         const float* __restrict__ bias,
         __nv_bfloat16* __restrict__ Oh, __nv_bfloat16* __restrict__ Ol,
         float* __restrict__ Ocf) {
    constexpr int CIC = 32;
    constexpr int KP = 40;
    constexpr int NCH = CH_ / CIC;
    constexpr int PPo = PP / 2;
    constexpr int TX = PP / 8;

    __shared__ alignas(16) __nv_bfloat16 s_ah[10][10][KP];
    __shared__ alignas(16) __nv_bfloat16 s_al[10][10][KP];
    __shared__ alignas(16) __nv_bfloat16 s_wh[9][32][KP];
    __shared__ alignas(16) __nv_bfloat16 s_wl[9][32][KP];

    const int tid = threadIdx.x;
    const int wrp = tid >> 5, lane = tid & 31;
    const int nimg = blockIdx.z;
    const int nb0 = blockIdx.y * 32;
    const int ty = blockIdx.x / TX, tx = blockIdx.x % TX;
    const int py0 = ty * 8, px0 = tx * 8;

    const int r1 = lane >> 2;
    const int kb = (lane & 3) * 2;
    const int seg = lane >> 3, lx8 = lane & 7;
    const int ay = 2 * wrp + (seg & 1);
    const int akoff = (seg >> 1) * 8;
    const int nrow0 = 8 * (seg >> 1) + lx8;
    const int bk0 = (seg & 1) * 8;

    const unsigned a_h_base = scvta(&s_ah[ay][lx8][akoff]);
    const unsigned a_l_base = scvta(&s_al[ay][lx8][akoff]);
    const unsigned b_h_base = scvta(&s_wh[0][nrow0][bk0]);
    const unsigned b_l_base = scvta(&s_wl[0][nrow0][bk0]);

    float acc[4][4];
#pragma unroll
    for (int f = 0; f < 4; f++)
#pragma unroll
        for (int q = 0; q < 4; q++) acc[f][q] = 0.f;

    for (int cc = 0; cc < NCH; cc++) {
        __syncthreads();
        for (int idx = tid; idx < 400; idx += 128) {
            int p = idx >> 2, q = idx & 3;
            int ly = p / 10, lx = p - ly * 10;
            int gy = py0 - 1 + ly, gx = px0 - 1 + lx;
            uint4 vh = make_uint4(0u, 0u, 0u, 0u), vl = vh;
            if ((unsigned)gy < (unsigned)PP && (unsigned)gx < (unsigned)PP) {
                size_t g = (((size_t)nimg * PP + gy) * PP + gx) * CH_ +
                           cc * CIC + q * 8;
                vh = *(const uint4*)(Ah + g);
                vl = *(const uint4*)(Al + g);
            }
            *(uint4*)&s_ah[ly][lx][q * 8] = vh;
            *(uint4*)&s_al[ly][lx][q * 8] = vl;
        }
        for (int idx = tid; idx < 1152; idx += 128) {
            int tap = idx >> 7, rem = idx & 127;
            int nn = rem >> 2, q = rem & 3;
            size_t g = ((size_t)tap * CH_ + nb0 + nn) * CH_ + cc * CIC + q * 8;
            *(uint4*)&s_wh[tap][nn][q * 8] = *(const uint4*)(Wh + g);
            *(uint4*)&s_wl[tap][nn][q * 8] = *(const uint4*)(Wl + g);
        }
        __syncthreads();

#pragma unroll
        for (int tap = 0; tap < 9; tap++) {
            const int ky = tap / 3, kx = tap % 3;
#pragma unroll
            for (int ks = 0; ks < 2; ks++) {
                const unsigned aoff = (unsigned)((ky * 10 + kx) * (KP * 2) + ks * 32);
                unsigned ah[4], al[4];
                ldsm4(ah, a_h_base + aoff);
                ldsm4(al, a_l_base + aoff);
#pragma unroll
                for (int fp = 0; fp < 4; fp += 2) {
                    const unsigned boff =
                        (unsigned)(tap * (32 * KP * 2) + fp * (8 * KP * 2) + ks * 32);
                    unsigned bh[4], bl[4];
                    ldsm4(bh, b_h_base + boff);
                    ldsm4(bl, b_l_base + boff);
                    mma16816(acc[fp], ah, bh[0], bh[1]);
                    mma16816(acc[fp], ah, bl[0], bl[1]);
                    mma16816(acc[fp], al, bh[0], bh[1]);
                    mma16816(acc[fp + 1], ah, bh[2], bh[3]);
                    mma16816(acc[fp + 1], ah, bl[2], bl[3]);
                    mma16816(acc[fp + 1], al, bh[2], bh[3]);
                }
            }
        }
    }

    const int Py = py0 / 2 + wrp;
    const int Px = px0 / 2 + (r1 >> 1);
    const bool writer = ((r1 & 1) == 0);
#pragma unroll
    for (int f = 0; f < 4; f++) {
        int ch = nb0 + f * 8 + kb;
        float v0 = fmaxf(acc[f][0], acc[f][2]);
        float v1 = fmaxf(acc[f][1], acc[f][3]);
        float o0 = fmaxf(v0, __shfl_xor_sync(0xffffffffu, v0, 4));
        float o1 = fmaxf(v1, __shfl_xor_sync(0xffffffffu, v1, 4));
        if (writer) {
            o0 = fmaxf(o0 + bias[ch], 0.f);
            o1 = fmaxf(o1 + bias[ch + 1], 0.f);
            if (OUT_CL) {
                size_t a = (((size_t)nimg * PPo + Py) * PPo + Px) * CH_ + ch;
                __nv_bfloat16 h0, l0, h1, l1;
                bsplit(o0, h0, l0);
                bsplit(o1, h1, l1);
                *(__nv_bfloat162*)(Oh + a) = __nv_bfloat162(h0, h1);
                *(__nv_bfloat162*)(Ol + a) = __nv_bfloat162(l0, l1);
            } else {
                size_t a = (((size_t)nimg * CH_ + ch) * PPo + Py) * PPo + Px;
                Ocf[a] = o0;
                Ocf[a + (size_t)PPo * PPo] = o1;
            }
        }
    }
}

// ---------------------------------------------------------------------------
// BatchNorm (batch stats) + affine + flatten.
// ---------------------------------------------------------------------------
__global__ void __launch_bounds__(256)
bn_flatten(const float* __restrict__ y4, const float* __restrict__ gamma,
           const float* __restrict__ beta, float* __restrict__ feat) {
    int c = blockIdx.x, tid = threadIdx.x;
    int i0 = tid * 4;
    int n = i0 >> 4, hw = i0 & 15;
    float4 v = *(const float4*)(y4 + (((size_t)n * 160 + c) << 4) + hw);
    float s = v.x + v.y + v.z + v.w;
    float q = v.x * v.x + v.y * v.y + v.z * v.z + v.w * v.w;
#pragma unroll
    for (int off = 16; off; off >>= 1) {
        s += __shfl_xor_sync(0xffffffffu, s, off);
        q += __shfl_xor_sync(0xffffffffu, q, off);
    }
    __shared__ float rs[8], rq[8];
    __shared__ float s_scale, s_shift;
    int w = tid >> 5, lane = tid & 31;
    if (!lane) { rs[w] = s; rq[w] = q; }
    __syncthreads();
    if (tid == 0) {
        float S = 0.f, Q = 0.f;
#pragma unroll
        for (int j = 0; j < 8; j++) { S += rs[j]; Q += rq[j]; }
        float mean = S * (1.f / 1024.f);
        float var = Q * (1.f / 1024.f) - mean * mean;
        float r = rsqrtf(var + EPS_);
        float g = gamma[c] * r;
        s_scale = g;
        s_shift = beta[c] - mean * g;
    }
    __syncthreads();
    float g = s_scale, b = s_shift;
    float4 o = make_float4(v.x * g + b, v.y * g + b, v.z * g + b, v.w * g + b);
    *(float4*)(feat + (size_t)n * 2560 + c * 16 + hw) = o;
}

// ---------------------------------------------------------------------------
// Routed linear: warp per output element.
// ---------------------------------------------------------------------------
template <bool RELU>
__global__ void __launch_bounds__(256)
fc_routed(const float* __restrict__ X, const float* __restrict__ Wb,
          const float* __restrict__ Bb, const int* __restrict__ act,
          float* __restrict__ Y, int IN, int OD) {
    int n = blockIdx.y;
    int w = threadIdx.x >> 5, lane = threadIdx.x & 31;
    int o = blockIdx.x * (blockDim.x >> 5) + w;
    if (o >= OD) return;
    int e = act[n];
    const float* wr = Wb + ((size_t)e * OD + o) * IN;
    const float* xr = X + (size_t)n * IN;
    float s = 0.f;
    for (int i = lane * 4; i < IN; i += 128) {
        float4 a = *(const float4*)(wr + i);
        float4 b = *(const float4*)(xr + i);
        s += a.x * b.x + a.y * b.y + a.z * b.z + a.w * b.w;
    }
#pragma unroll
    for (int off = 16; off; off >>= 1) s += __shfl_xor_sync(0xffffffffu, s, off);
    if (!lane) {
        float v = s + Bb[(size_t)e * OD + o];
        if (RELU) v = fmaxf(v, 0.f);
        Y[(size_t)n * OD + o] = v;
    }
}

// ---------------------------------------------------------------------------
extern "C" void kernel_launch(void* const* d_in, const int* in_sizes, int n_in,
                              void* d_out, int out_size) {
    const float* x   = (const float*)d_in[0];
    const int* a1    = (const int*)d_in[1];
    const int* a2    = (const int*)d_in[2];
    const int* a3    = (const int*)d_in[3];
    const float* W1  = (const float*)d_in[4];
    const float* b1  = (const float*)d_in[5];
    const float* W2  = (const float*)d_in[6];
    const float* b2  = (const float*)d_in[7];
    const float* W3  = (const float*)d_in[8];
    const float* b3  = (const float*)d_in[9];
    const float* W4  = (const float*)d_in[10];
    const float* b4  = (const float*)d_in[11];
    const float* gam = (const float*)d_in[12];
    const float* bet = (const float*)d_in[13];
    const float* E1W = (const float*)d_in[14];
    const float* E1b = (const float*)d_in[15];
    const float* E2W = (const float*)d_in[16];
    const float* E2b = (const float*)d_in[17];
    const float* E3W = (const float*)d_in[18];
    const float* E3b = (const float*)d_in[19];
    float* out = (float*)d_out;

    __nv_bfloat16 *y1h, *y1l, *y2h, *y2l, *y3h, *y3l;
    __nv_bfloat16 *w1h, *w1l, *w2h, *w2l, *w3h, *w3l, *w4h, *w4l;
    float *y4, *feat, *h1, *h2;
    cudaGetSymbolAddress((void**)&y1h, g_y1h);
    cudaGetSymbolAddress((void**)&y1l, g_y1l);
    cudaGetSymbolAddress((void**)&y2h, g_y2h);
    cudaGetSymbolAddress((void**)&y2l, g_y2l);
    cudaGetSymbolAddress((void**)&y3h, g_y3h);
    cudaGetSymbolAddress((void**)&y3l, g_y3l);
    cudaGetSymbolAddress((void**)&w1h, g_w1h);
    cudaGetSymbolAddress((void**)&w1l, g_w1l);
    cudaGetSymbolAddress((void**)&w2h, g_w2h);
    cudaGetSymbolAddress((void**)&w2l, g_w2l);
    cudaGetSymbolAddress((void**)&w3h, g_w3h);
    cudaGetSymbolAddress((void**)&w3l, g_w3l);
    cudaGetSymbolAddress((void**)&w4h, g_w4h);
    cudaGetSymbolAddress((void**)&w4l, g_w4l);
    cudaGetSymbolAddress((void**)&y4, g_y4);
    cudaGetSymbolAddress((void**)&feat, g_feat);
    cudaGetSymbolAddress((void**)&h1, g_h1);
    cudaGetSymbolAddress((void**)&h2, g_h2);

    // weight pre-splits
    int nsplit = (9 * CH_ * CH_ + 255) / 256;
    presplit_w1<<<(CH_ * 32 + 255) / 256, 256>>>(W1, w1h, w1l);
    presplit_w<<<nsplit, 256>>>(W2, w2h, w2l);
    presplit_w<<<nsplit, 256>>>(W3, w3h, w3l);
    presplit_w<<<nsplit, 256>>>(W4, w4h, w4l);

    // conv1 tensor (im2col, K=32 single chunk): 64x64 -> pooled 32x32
    conv1_mma<<<dim3(64, 5, 64), 128>>>(x, w1h, w1l, b1, y1h, y1l);
    // conv2 tensor: 32x32 prepool -> 16x16, CL bf16 out
    conv_mma<32, true><<<dim3(16, 5, 64), 128>>>(
        y1h, y1l, w2h, w2l, b2, y2h, y2l, nullptr);
    // conv3 tensor: 16x16 prepool -> 8x8, CL bf16 out
    conv_mma<16, true><<<dim3(4, 5, 64), 128>>>(
        y2h, y2l, w3h, w3l, b3, y3h, y3l, nullptr);
    // conv4 tensor: 8x8 prepool -> 4x4, fp32 channel-first out
    conv_mma<8, false><<<dim3(1, 5, 64), 128>>>(
        y3h, y3l, w4h, w4l, b4, nullptr, nullptr, y4);

    bn_flatten<<<160, 256>>>(y4, gam, bet, feat);

    fc_routed<true ><<<dim3(40, 64), 256>>>(feat, E1W, E1b, a1, h1, 2560, 320);
    fc_routed<true ><<<dim3(40, 64), 256>>>(h1,   E2W, E2b, a2, h2, 320, 320);
    fc_routed<false><<<dim3(2, 64),  256>>>(h2,   E3W, E3b, a3, out, 320, 10);
}

// round 12
// speedup vs baseline: 2.2421x; 1.0228x over previous
#include <cuda_runtime.h>
#include <cuda_bf16.h>
#include <cstdint>
#include <cstddef>

// ---------------------------------------------------------------------------
// RoutedAllFC round 12: conv_mma batches IMGS=4 images per block to amortize
// weight staging 4x (the dominant L2 traffic). 512 thr, dynamic smem 110KB,
// per-warp MMA code identical to validated r10 version. conv1 im2col GEMM.
// ---------------------------------------------------------------------------

#define B_   64
#define CH_  160
#define EPS_ 1e-5f

// activations, channel-last bf16 hi/lo splits
__device__ __nv_bfloat16 g_y1h[B_ * 32 * 32 * CH_];
__device__ __nv_bfloat16 g_y1l[B_ * 32 * 32 * CH_];
__device__ __nv_bfloat16 g_y2h[B_ * 16 * 16 * CH_];
__device__ __nv_bfloat16 g_y2l[B_ * 16 * 16 * CH_];
__device__ __nv_bfloat16 g_y3h[B_ * 8 * 8 * CH_];
__device__ __nv_bfloat16 g_y3l[B_ * 8 * 8 * CH_];
// weights pre-split to bf16 hi/lo
__device__ __nv_bfloat16 g_w1h[CH_ * 32];         // [co][k=ci*9+tap, pad 32]
__device__ __nv_bfloat16 g_w1l[CH_ * 32];
__device__ __nv_bfloat16 g_w2h[9 * CH_ * CH_];    // [tap][co][ci]
__device__ __nv_bfloat16 g_w2l[9 * CH_ * CH_];
__device__ __nv_bfloat16 g_w3h[9 * CH_ * CH_];
__device__ __nv_bfloat16 g_w3l[9 * CH_ * CH_];
__device__ __nv_bfloat16 g_w4h[9 * CH_ * CH_];
__device__ __nv_bfloat16 g_w4l[9 * CH_ * CH_];
// fp32 tail
__device__ float g_y4[B_ * CH_ * 4 * 4];
__device__ float g_feat[B_ * 2560];
__device__ float g_h1[B_ * 320];
__device__ float g_h2[B_ * 320];

// ---- bf16 split -------------------------------------------------------------
__device__ __forceinline__ void bsplit(float v, __nv_bfloat16& h, __nv_bfloat16& l) {
    h = __float2bfloat16(v);
    l = __float2bfloat16(v - __bfloat162float(h));
}

// ---- mma + ldmatrix ----------------------------------------------------------
__device__ __forceinline__ void mma16816(float* c, const unsigned* a,
                                         unsigned b0, unsigned b1) {
    asm("mma.sync.aligned.m16n8k16.row.col.f32.bf16.bf16.f32 "
        "{%0,%1,%2,%3},{%4,%5,%6,%7},{%8,%9},{%0,%1,%2,%3};"
        : "+f"(c[0]), "+f"(c[1]), "+f"(c[2]), "+f"(c[3])
        : "r"(a[0]), "r"(a[1]), "r"(a[2]), "r"(a[3]), "r"(b0), "r"(b1));
}
__device__ __forceinline__ void ldsm4(unsigned* r, unsigned addr) {
    asm volatile("ldmatrix.sync.aligned.m8n8.x4.shared.b16 {%0,%1,%2,%3}, [%4];"
                 : "=r"(r[0]), "=r"(r[1]), "=r"(r[2]), "=r"(r[3]) : "r"(addr));
}
__device__ __forceinline__ unsigned scvta(const void* p) {
    return (unsigned)__cvta_generic_to_shared(p);
}

// ---------------------------------------------------------------------------
// weight pre-splits
// ---------------------------------------------------------------------------
__global__ void __launch_bounds__(256)
presplit_w(const float* __restrict__ W, __nv_bfloat16* __restrict__ Wh,
           __nv_bfloat16* __restrict__ Wl) {
    int idx = blockIdx.x * 256 + threadIdx.x;
    if (idx >= 9 * CH_ * CH_) return;
    int tap = idx / (CH_ * CH_);
    int r = idx - tap * (CH_ * CH_);
    int co = r / CH_, ci = r - co * CH_;
    float w = W[(co * CH_ + ci) * 9 + tap];
    __nv_bfloat16 h, l;
    bsplit(w, h, l);
    Wh[idx] = h;
    Wl[idx] = l;
}

__global__ void __launch_bounds__(256)
presplit_w1(const float* __restrict__ W, __nv_bfloat16* __restrict__ Wh,
            __nv_bfloat16* __restrict__ Wl) {
    int idx = blockIdx.x * 256 + threadIdx.x;
    if (idx >= CH_ * 32) return;
    int co = idx >> 5, k = idx & 31;
    float w = (k < 27) ? W[co * 27 + k] : 0.f;
    __nv_bfloat16 h, l;
    bsplit(w, h, l);
    Wh[idx] = h;
    Wl[idx] = l;
}

// ---------------------------------------------------------------------------
// conv1 tensor: im2col GEMM (K=27 pad 32, single chunk). Unchanged from r11.
// ---------------------------------------------------------------------------
__global__ void __launch_bounds__(128)
conv1_mma(const float* __restrict__ x,
          const __nv_bfloat16* __restrict__ Wh, const __nv_bfloat16* __restrict__ Wl,
          const float* __restrict__ bias,
          __nv_bfloat16* __restrict__ Oh, __nv_bfloat16* __restrict__ Ol) {
    constexpr int KP = 40;
    __shared__ float s_halo[3][10][10];
    __shared__ alignas(16) __nv_bfloat16 s_ah[64][KP];
    __shared__ alignas(16) __nv_bfloat16 s_al[64][KP];
    __shared__ alignas(16) __nv_bfloat16 s_wh[32][KP];
    __shared__ alignas(16) __nv_bfloat16 s_wl[32][KP];

    const int tid = threadIdx.x;
    const int wrp = tid >> 5, lane = tid & 31;
    const int nimg = blockIdx.z;
    const int nb0 = blockIdx.y * 32;
    const int ty = blockIdx.x >> 3, tx = blockIdx.x & 7;
    const int py0 = ty * 8, px0 = tx * 8;

    for (int idx = tid; idx < 300; idx += 128) {
        int ci = idx / 100, rem = idx - ci * 100;
        int ly = rem / 10, lx = rem - ly * 10;
        int gy = py0 - 1 + ly, gx = px0 - 1 + lx;
        float v = 0.f;
        if ((unsigned)gy < 64u && (unsigned)gx < 64u)
            v = x[(((size_t)nimg * 3 + ci) * 64 + gy) * 64 + gx];
        s_halo[ci][ly][lx] = v;
    }
    for (int idx = tid; idx < 1024; idx += 128) {
        int nn = idx >> 5, k = idx & 31;
        s_wh[nn][k] = Wh[(nb0 + nn) * 32 + k];
        s_wl[nn][k] = Wl[(nb0 + nn) * 32 + k];
    }
    __syncthreads();

    for (int idx = tid; idx < 2048; idx += 128) {
        int m = idx >> 5, k = idx & 31;
        int yy = m >> 3, xx = m & 7;
        float v = 0.f;
        if (k < 27) {
            int ci = k / 9, tap = k - ci * 9;
            int ky = tap / 3, kx = tap - ky * 3;
            v = s_halo[ci][yy + ky][xx + kx];
        }
        __nv_bfloat16 h, l;
        bsplit(v, h, l);
        s_ah[m][k] = h;
        s_al[m][k] = l;
    }
    __syncthreads();

    const int r1 = lane >> 2;
    const int kb = (lane & 3) * 2;
    const int seg = lane >> 3, lx8 = lane & 7;
    const unsigned a_h_base = scvta(&s_ah[16 * wrp + (seg & 1) * 8 + lx8][(seg >> 1) * 8]);
    const unsigned a_l_base = scvta(&s_al[16 * wrp + (seg & 1) * 8 + lx8][(seg >> 1) * 8]);
    const int nrow0 = 8 * (seg >> 1) + lx8;
    const int bk0 = (seg & 1) * 8;
    const unsigned b_h_base = scvta(&s_wh[nrow0][bk0]);
    const unsigned b_l_base = scvta(&s_wl[nrow0][bk0]);

    float acc[4][4];
#pragma unroll
    for (int f = 0; f < 4; f++)
#pragma unroll
        for (int q = 0; q < 4; q++) acc[f][q] = 0.f;

#pragma unroll
    for (int ks = 0; ks < 2; ks++) {
        unsigned ah[4], al[4];
        ldsm4(ah, a_h_base + ks * 32);
        ldsm4(al, a_l_base + ks * 32);
#pragma unroll
        for (int fp = 0; fp < 4; fp += 2) {
            const unsigned boff = (unsigned)(fp * (8 * KP * 2) + ks * 32);
            unsigned bh[4], bl[4];
            ldsm4(bh, b_h_base + boff);
            ldsm4(bl, b_l_base + boff);
            mma16816(acc[fp], ah, bh[0], bh[1]);
            mma16816(acc[fp], ah, bl[0], bl[1]);
            mma16816(acc[fp], al, bh[0], bh[1]);
            mma16816(acc[fp + 1], ah, bh[2], bh[3]);
            mma16816(acc[fp + 1], ah, bl[2], bl[3]);
            mma16816(acc[fp + 1], al, bh[2], bh[3]);
        }
    }

    const int Py = py0 / 2 + wrp;
    const int Px = px0 / 2 + (r1 >> 1);
    const bool writer = ((r1 & 1) == 0);
#pragma unroll
    for (int f = 0; f < 4; f++) {
        int ch = nb0 + f * 8 + kb;
        float v0 = fmaxf(acc[f][0], acc[f][2]);
        float v1 = fmaxf(acc[f][1], acc[f][3]);
        float o0 = fmaxf(v0, __shfl_xor_sync(0xffffffffu, v0, 4));
        float o1 = fmaxf(v1, __shfl_xor_sync(0xffffffffu, v1, 4));
        if (writer) {
            o0 = fmaxf(o0 + bias[ch], 0.f);
            o1 = fmaxf(o1 + bias[ch + 1], 0.f);
            size_t a = (((size_t)nimg * 32 + Py) * 32 + Px) * CH_ + ch;
            __nv_bfloat16 h0, l0, h1, l1;
            bsplit(o0, h0, l0);
            bsplit(o1, h1, l1);
            *(__nv_bfloat162*)(Oh + a) = __nv_bfloat162(h0, h1);
            *(__nv_bfloat162*)(Ol + a) = __nv_bfloat162(l0, l1);
        }
    }
}

// ---------------------------------------------------------------------------
// Tensor-core conv3x3+bias+ReLU+maxpool2, IMGS images per block (weights
// staged once per chunk for all IMGS). 128*IMGS threads; warp w handles
// image w>>2, tile-quarter w&3 (per-warp code identical to r10 version).
// Dynamic smem: [ah | al | wh | wl].
// ---------------------------------------------------------------------------
template <int PP, int IMGS, bool OUT_CL>
__global__ void __launch_bounds__(128 * IMGS, 1)
conv_mma(const __nv_bfloat16* __restrict__ Ah, const __nv_bfloat16* __restrict__ Al,
         const __nv_bfloat16* __restrict__ Wh, const __nv_bfloat16* __restrict__ Wl,
         const float* __restrict__ bias,
         __nv_bfloat16* __restrict__ Oh, __nv_bfloat16* __restrict__ Ol,
         float* __restrict__ Ocf) {
    constexpr int CIC = 32;
    constexpr int KP = 40;
    constexpr int NCH = CH_ / CIC;
    constexpr int PPo = PP / 2;
    constexpr int TX = PP / 8;
    constexpr int T = 128 * IMGS;
    constexpr int A_ELEMS = IMGS * 100 * KP;
    constexpr int W_ELEMS = 9 * 32 * KP;

    extern __shared__ __align__(16) __nv_bfloat16 smem[];
    __nv_bfloat16* s_ah = smem;
    __nv_bfloat16* s_al = s_ah + A_ELEMS;
    __nv_bfloat16* s_wh = s_al + A_ELEMS;
    __nv_bfloat16* s_wl = s_wh + W_ELEMS;

    const int tid = threadIdx.x;
    const int wrp = tid >> 5, lane = tid & 31;
    const int im = wrp >> 2, w4 = wrp & 3;
    const int img0 = blockIdx.z * IMGS;
    const int nb0 = blockIdx.y * 32;
    const int ty = blockIdx.x / TX, tx = blockIdx.x % TX;
    const int py0 = ty * 8, px0 = tx * 8;

    const int r1 = lane >> 2;
    const int kb = (lane & 3) * 2;
    const int seg = lane >> 3, lx8 = lane & 7;
    const int ay = 2 * w4 + (seg & 1);
    const int akoff = (seg >> 1) * 8;
    const int nrow0 = 8 * (seg >> 1) + lx8;
    const int bk0 = (seg & 1) * 8;

    const unsigned a_h_base = scvta(&s_ah[(im * 100 + ay * 10 + lx8) * KP + akoff]);
    const unsigned a_l_base = scvta(&s_al[(im * 100 + ay * 10 + lx8) * KP + akoff]);
    const unsigned b_h_base = scvta(&s_wh[nrow0 * KP + bk0]);
    const unsigned b_l_base = scvta(&s_wl[nrow0 * KP + bk0]);

    float acc[4][4];
#pragma unroll
    for (int f = 0; f < 4; f++)
#pragma unroll
        for (int q = 0; q < 4; q++) acc[f][q] = 0.f;

    for (int cc = 0; cc < NCH; cc++) {
        __syncthreads();
        // stage A for IMGS images (10x10 halo x 32ch, hi+lo), zero-padded
        for (int idx = tid; idx < IMGS * 400; idx += T) {
            int aim = idx / 400, rem = idx - aim * 400;
            int p = rem >> 2, q = rem & 3;
            int ly = p / 10, lx = p - ly * 10;
            int gy = py0 - 1 + ly, gx = px0 - 1 + lx;
            uint4 vh = make_uint4(0u, 0u, 0u, 0u), vl = vh;
            if ((unsigned)gy < (unsigned)PP && (unsigned)gx < (unsigned)PP) {
                size_t g = (((size_t)(img0 + aim) * PP + gy) * PP + gx) * CH_ +
                           cc * CIC + q * 8;
                vh = *(const uint4*)(Ah + g);
                vl = *(const uint4*)(Al + g);
            }
            int base = (aim * 100 + ly * 10 + lx) * KP + q * 8;
            *(uint4*)&s_ah[base] = vh;
            *(uint4*)&s_al[base] = vl;
        }
        // stage weights [tap][n32][32] hi+lo (once for all IMGS images)
        for (int idx = tid; idx < 1152; idx += T) {
            int tap = idx >> 7, rem = idx & 127;
            int nn = rem >> 2, q = rem & 3;
            size_t g = ((size_t)tap * CH_ + nb0 + nn) * CH_ + cc * CIC + q * 8;
            int base = (tap * 32 + nn) * KP + q * 8;
            *(uint4*)&s_wh[base] = *(const uint4*)(Wh + g);
            *(uint4*)&s_wl[base] = *(const uint4*)(Wl + g);
        }
        __syncthreads();

#pragma unroll
        for (int tap = 0; tap < 9; tap++) {
            const int ky = tap / 3, kx = tap % 3;
#pragma unroll
            for (int ks = 0; ks < 2; ks++) {
                const unsigned aoff = (unsigned)((ky * 10 + kx) * (KP * 2) + ks * 32);
                unsigned ah[4], al[4];
                ldsm4(ah, a_h_base + aoff);
                ldsm4(al, a_l_base + aoff);
#pragma unroll
                for (int fp = 0; fp < 4; fp += 2) {
                    const unsigned boff =
                        (unsigned)(tap * (32 * KP * 2) + fp * (8 * KP * 2) + ks * 32);
                    unsigned bh[4], bl[4];
                    ldsm4(bh, b_h_base + boff);
                    ldsm4(bl, b_l_base + boff);
                    mma16816(acc[fp], ah, bh[0], bh[1]);
                    mma16816(acc[fp], ah, bl[0], bl[1]);
                    mma16816(acc[fp], al, bh[0], bh[1]);
                    mma16816(acc[fp + 1], ah, bh[2], bh[3]);
                    mma16816(acc[fp + 1], ah, bl[2], bl[3]);
                    mma16816(acc[fp + 1], al, bh[2], bh[3]);
                }
            }
        }
    }

    const int nimg = img0 + im;
    const int Py = py0 / 2 + w4;
    const int Px = px0 / 2 + (r1 >> 1);
    const bool writer = ((r1 & 1) == 0);
#pragma unroll
    for (int f = 0; f < 4; f++) {
        int ch = nb0 + f * 8 + kb;
        float v0 = fmaxf(acc[f][0], acc[f][2]);
        float v1 = fmaxf(acc[f][1], acc[f][3]);
        float o0 = fmaxf(v0, __shfl_xor_sync(0xffffffffu, v0, 4));
        float o1 = fmaxf(v1, __shfl_xor_sync(0xffffffffu, v1, 4));
        if (writer) {
            o0 = fmaxf(o0 + bias[ch], 0.f);
            o1 = fmaxf(o1 + bias[ch + 1], 0.f);
            if (OUT_CL) {
                size_t a = (((size_t)nimg * PPo + Py) * PPo + Px) * CH_ + ch;
                __nv_bfloat16 h0, l0, h1, l1;
                bsplit(o0, h0, l0);
                bsplit(o1, h1, l1);
                *(__nv_bfloat162*)(Oh + a) = __nv_bfloat162(h0, h1);
                *(__nv_bfloat162*)(Ol + a) = __nv_bfloat162(l0, l1);
            } else {
                size_t a = (((size_t)nimg * CH_ + ch) * PPo + Py) * PPo + Px;
                Ocf[a] = o0;
                Ocf[a + (size_t)PPo * PPo] = o1;
            }
        }
    }
}

// ---------------------------------------------------------------------------
// BatchNorm (batch stats) + affine + flatten.
// ---------------------------------------------------------------------------
__global__ void __launch_bounds__(256)
bn_flatten(const float* __restrict__ y4, const float* __restrict__ gamma,
           const float* __restrict__ beta, float* __restrict__ feat) {
    int c = blockIdx.x, tid = threadIdx.x;
    int i0 = tid * 4;
    int n = i0 >> 4, hw = i0 & 15;
    float4 v = *(const float4*)(y4 + (((size_t)n * 160 + c) << 4) + hw);
    float s = v.x + v.y + v.z + v.w;
    float q = v.x * v.x + v.y * v.y + v.z * v.z + v.w * v.w;
#pragma unroll
    for (int off = 16; off; off >>= 1) {
        s += __shfl_xor_sync(0xffffffffu, s, off);
        q += __shfl_xor_sync(0xffffffffu, q, off);
    }
    __shared__ float rs[8], rq[8];
    __shared__ float s_scale, s_shift;
    int w = tid >> 5, lane = tid & 31;
    if (!lane) { rs[w] = s; rq[w] = q; }
    __syncthreads();
    if (tid == 0) {
        float S = 0.f, Q = 0.f;
#pragma unroll
        for (int j = 0; j < 8; j++) { S += rs[j]; Q += rq[j]; }
        float mean = S * (1.f / 1024.f);
        float var = Q * (1.f / 1024.f) - mean * mean;
        float r = rsqrtf(var + EPS_);
        float g = gamma[c] * r;
        s_scale = g;
        s_shift = beta[c] - mean * g;
    }
    __syncthreads();
    float g = s_scale, b = s_shift;
    float4 o = make_float4(v.x * g + b, v.y * g + b, v.z * g + b, v.w * g + b);
    *(float4*)(feat + (size_t)n * 2560 + c * 16 + hw) = o;
}

// ---------------------------------------------------------------------------
// Routed linear: warp per output element.
// ---------------------------------------------------------------------------
template <bool RELU>
__global__ void __launch_bounds__(256)
fc_routed(const float* __restrict__ X, const float* __restrict__ Wb,
          const float* __restrict__ Bb, const int* __restrict__ act,
          float* __restrict__ Y, int IN, int OD) {
    int n = blockIdx.y;
    int w = threadIdx.x >> 5, lane = threadIdx.x & 31;
    int o = blockIdx.x * (blockDim.x >> 5) + w;
    if (o >= OD) return;
    int e = act[n];
    const float* wr = Wb + ((size_t)e * OD + o) * IN;
    const float* xr = X + (size_t)n * IN;
    float s = 0.f;
    for (int i = lane * 4; i < IN; i += 128) {
        float4 a = *(const float4*)(wr + i);
        float4 b = *(const float4*)(xr + i);
        s += a.x * b.x + a.y * b.y + a.z * b.z + a.w * b.w;
    }
#pragma unroll
    for (int off = 16; off; off >>= 1) s += __shfl_xor_sync(0xffffffffu, s, off);
    if (!lane) {
        float v = s + Bb[(size_t)e * OD + o];
        if (RELU) v = fmaxf(v, 0.f);
        Y[(size_t)n * OD + o] = v;
    }
}

// ---------------------------------------------------------------------------
extern "C" void kernel_launch(void* const* d_in, const int* in_sizes, int n_in,
                              void* d_out, int out_size) {
    const float* x   = (const float*)d_in[0];
    const int* a1    = (const int*)d_in[1];
    const int* a2    = (const int*)d_in[2];
    const int* a3    = (const int*)d_in[3];
    const float* W1  = (const float*)d_in[4];
    const float* b1  = (const float*)d_in[5];
    const float* W2  = (const float*)d_in[6];
    const float* b2  = (const float*)d_in[7];
    const float* W3  = (const float*)d_in[8];
    const float* b3  = (const float*)d_in[9];
    const float* W4  = (const float*)d_in[10];
    const float* b4  = (const float*)d_in[11];
    const float* gam = (const float*)d_in[12];
    const float* bet = (const float*)d_in[13];
    const float* E1W = (const float*)d_in[14];
    const float* E1b = (const float*)d_in[15];
    const float* E2W = (const float*)d_in[16];
    const float* E2b = (const float*)d_in[17];
    const float* E3W = (const float*)d_in[18];
    const float* E3b = (const float*)d_in[19];
    float* out = (float*)d_out;

    __nv_bfloat16 *y1h, *y1l, *y2h, *y2l, *y3h, *y3l;
    __nv_bfloat16 *w1h, *w1l, *w2h, *w2l, *w3h, *w3l, *w4h, *w4l;
    float *y4, *feat, *h1, *h2;
    cudaGetSymbolAddress((void**)&y1h, g_y1h);
    cudaGetSymbolAddress((void**)&y1l, g_y1l);
    cudaGetSymbolAddress((void**)&y2h, g_y2h);
    cudaGetSymbolAddress((void**)&y2l, g_y2l);
    cudaGetSymbolAddress((void**)&y3h, g_y3h);
    cudaGetSymbolAddress((void**)&y3l, g_y3l);
    cudaGetSymbolAddress((void**)&w1h, g_w1h);
    cudaGetSymbolAddress((void**)&w1l, g_w1l);
    cudaGetSymbolAddress((void**)&w2h, g_w2h);
    cudaGetSymbolAddress((void**)&w2l, g_w2l);
    cudaGetSymbolAddress((void**)&w3h, g_w3h);
    cudaGetSymbolAddress((void**)&w3l, g_w3l);
    cudaGetSymbolAddress((void**)&w4h, g_w4h);
    cudaGetSymbolAddress((void**)&w4l, g_w4l);
    cudaGetSymbolAddress((void**)&y4, g_y4);
    cudaGetSymbolAddress((void**)&feat, g_feat);
    cudaGetSymbolAddress((void**)&h1, g_h1);
    cudaGetSymbolAddress((void**)&h2, g_h2);

    // dynamic smem sizes for conv_mma<*, 4, *>
    constexpr int SMEM_CONV = (2 * (4 * 100 * 40) + 2 * (9 * 32 * 40)) * 2;  // 110080
    static bool attr_set = false;
    if (!attr_set) {
        cudaFuncSetAttribute(conv_mma<32, 4, true>,
                             cudaFuncAttributeMaxDynamicSharedMemorySize, SMEM_CONV);
        cudaFuncSetAttribute(conv_mma<16, 4, true>,
                             cudaFuncAttributeMaxDynamicSharedMemorySize, SMEM_CONV);
        cudaFuncSetAttribute(conv_mma<8, 4, false>,
                             cudaFuncAttributeMaxDynamicSharedMemorySize, SMEM_CONV);
        attr_set = true;
    }

    // weight pre-splits
    int nsplit = (9 * CH_ * CH_ + 255) / 256;
    presplit_w1<<<(CH_ * 32 + 255) / 256, 256>>>(W1, w1h, w1l);
    presplit_w<<<nsplit, 256>>>(W2, w2h, w2l);
    presplit_w<<<nsplit, 256>>>(W3, w3h, w3l);
    presplit_w<<<nsplit, 256>>>(W4, w4h, w4l);

    // conv1 tensor (im2col): 64x64 -> pooled 32x32
    conv1_mma<<<dim3(64, 5, 64), 128>>>(x, w1h, w1l, b1, y1h, y1l);
    // conv2 tensor, 4 images/block: 32x32 prepool -> 16x16
    conv_mma<32, 4, true><<<dim3(16, 5, 16), 512, SMEM_CONV>>>(
        y1h, y1l, w2h, w2l, b2, y2h, y2l, nullptr);
    // conv3 tensor, 4 images/block: 16x16 prepool -> 8x8
    conv_mma<16, 4, true><<<dim3(4, 5, 16), 512, SMEM_CONV>>>(
        y2h, y2l, w3h, w3l, b3, y3h, y3l, nullptr);
    // conv4 tensor, 4 images/block: 8x8 prepool -> 4x4, fp32 chan-first out
    conv_mma<8, 4, false><<<dim3(1, 5, 16), 512, SMEM_CONV>>>(
        y3h, y3l, w4h, w4l, b4, nullptr, nullptr, y4);

    bn_flatten<<<160, 256>>>(y4, gam, bet, feat);

    fc_routed<true ><<<dim3(40, 64), 256>>>(feat, E1W, E1b, a1, h1, 2560, 320);
    fc_routed<true ><<<dim3(40, 64), 256>>>(h1,   E2W, E2b, a2, h2, 320, 320);
    fc_routed<false><<<dim3(2, 64),  256>>>(h2,   E3W, E3b, a3, out, 320, 10);
}

// round 13
// speedup vs baseline: 3.2088x; 1.4311x over previous
#include <cuda_runtime.h>
#include <cuda_fp16.h>
#include <cstdint>
#include <cstddef>

// ---------------------------------------------------------------------------
// RoutedAllFC round 13: fp16 2-product scheme. Activations hi/lo fp16 split
// (error 2^-22); weights SINGLE fp16 (error 2^-12 RMS) -> 2 mma per fragment
// instead of 3, wl staging eliminated, smem 110->87KB (2 blocks/SM).
// ---------------------------------------------------------------------------

#define B_   64
#define CH_  160
#define EPS_ 1e-5f

// activations, channel-last fp16 hi/lo splits
__device__ __half g_y1h[B_ * 32 * 32 * CH_];
__device__ __half g_y1l[B_ * 32 * 32 * CH_];
__device__ __half g_y2h[B_ * 16 * 16 * CH_];
__device__ __half g_y2l[B_ * 16 * 16 * CH_];
__device__ __half g_y3h[B_ * 8 * 8 * CH_];
__device__ __half g_y3l[B_ * 8 * 8 * CH_];
// weights, single fp16
__device__ __half g_w1[CH_ * 32];         // [co][k=ci*9+tap, pad 32]
__device__ __half g_w2[9 * CH_ * CH_];    // [tap][co][ci]
__device__ __half g_w3[9 * CH_ * CH_];
__device__ __half g_w4[9 * CH_ * CH_];
// fp32 tail
__device__ float g_y4[B_ * CH_ * 4 * 4];
__device__ float g_feat[B_ * 2560];
__device__ float g_h1[B_ * 320];
__device__ float g_h2[B_ * 320];

// ---- fp16 split --------------------------------------------------------------
__device__ __forceinline__ void hsplit(float v, __half& h, __half& l) {
    h = __float2half_rn(v);
    l = __float2half_rn(v - __half2float(h));
}

// ---- mma + ldmatrix ----------------------------------------------------------
__device__ __forceinline__ void mma16816(float* c, const unsigned* a,
                                         unsigned b0, unsigned b1) {
    asm("mma.sync.aligned.m16n8k16.row.col.f32.f16.f16.f32 "
        "{%0,%1,%2,%3},{%4,%5,%6,%7},{%8,%9},{%0,%1,%2,%3};"
        : "+f"(c[0]), "+f"(c[1]), "+f"(c[2]), "+f"(c[3])
        : "r"(a[0]), "r"(a[1]), "r"(a[2]), "r"(a[3]), "r"(b0), "r"(b1));
}
__device__ __forceinline__ void ldsm4(unsigned* r, unsigned addr) {
    asm volatile("ldmatrix.sync.aligned.m8n8.x4.shared.b16 {%0,%1,%2,%3}, [%4];"
                 : "=r"(r[0]), "=r"(r[1]), "=r"(r[2]), "=r"(r[3]) : "r"(addr));
}
__device__ __forceinline__ unsigned scvta(const void* p) {
    return (unsigned)__cvta_generic_to_shared(p);
}

// ---------------------------------------------------------------------------
// weight converts: fp32 [co][ci][3][3] -> fp16 [tap][co][ci], 3 layers in one
// launch (blockIdx.y selects layer).
// ---------------------------------------------------------------------------
__global__ void __launch_bounds__(256)
pre_w(const float* __restrict__ W2, const float* __restrict__ W3,
      const float* __restrict__ W4, __half* __restrict__ O2,
      __half* __restrict__ O3, __half* __restrict__ O4) {
    int idx = blockIdx.x * 256 + threadIdx.x;
    if (idx >= 9 * CH_ * CH_) return;
    const float* W = (blockIdx.y == 0) ? W2 : (blockIdx.y == 1) ? W3 : W4;
    __half* O = (blockIdx.y == 0) ? O2 : (blockIdx.y == 1) ? O3 : O4;
    int tap = idx / (CH_ * CH_);
    int r = idx - tap * (CH_ * CH_);
    int co = r / CH_, ci = r - co * CH_;
    O[idx] = __float2half_rn(W[(co * CH_ + ci) * 9 + tap]);
}

__global__ void __launch_bounds__(256)
pre_w1(const float* __restrict__ W, __half* __restrict__ O) {
    int idx = blockIdx.x * 256 + threadIdx.x;
    if (idx >= CH_ * 32) return;
    int co = idx >> 5, k = idx & 31;
    O[idx] = __float2half_rn((k < 27) ? W[co * 27 + k] : 0.f);
}

// ---------------------------------------------------------------------------
// conv1 tensor: im2col GEMM (K=27 pad 32, single chunk), fp16 2-product.
// ---------------------------------------------------------------------------
__global__ void __launch_bounds__(128)
conv1_mma(const float* __restrict__ x, const __half* __restrict__ Wt,
          const float* __restrict__ bias,
          __half* __restrict__ Oh, __half* __restrict__ Ol) {
    constexpr int KP = 40;
    __shared__ float s_halo[3][10][10];
    __shared__ alignas(16) __half s_ah[64][KP];
    __shared__ alignas(16) __half s_al[64][KP];
    __shared__ alignas(16) __half s_w[32][KP];

    const int tid = threadIdx.x;
    const int wrp = tid >> 5, lane = tid & 31;
    const int nimg = blockIdx.z;
    const int nb0 = blockIdx.y * 32;
    const int ty = blockIdx.x >> 3, tx = blockIdx.x & 7;
    const int py0 = ty * 8, px0 = tx * 8;

    for (int idx = tid; idx < 300; idx += 128) {
        int ci = idx / 100, rem = idx - ci * 100;
        int ly = rem / 10, lx = rem - ly * 10;
        int gy = py0 - 1 + ly, gx = px0 - 1 + lx;
        float v = 0.f;
        if ((unsigned)gy < 64u && (unsigned)gx < 64u)
            v = x[(((size_t)nimg * 3 + ci) * 64 + gy) * 64 + gx];
        s_halo[ci][ly][lx] = v;
    }
    for (int idx = tid; idx < 1024; idx += 128) {
        int nn = idx >> 5, k = idx & 31;
        s_w[nn][k] = Wt[(nb0 + nn) * 32 + k];
    }
    __syncthreads();

    for (int idx = tid; idx < 2048; idx += 128) {
        int m = idx >> 5, k = idx & 31;
        int yy = m >> 3, xx = m & 7;
        float v = 0.f;
        if (k < 27) {
            int ci = k / 9, tap = k - ci * 9;
            int ky = tap / 3, kx = tap - ky * 3;
            v = s_halo[ci][yy + ky][xx + kx];
        }
        __half h, l;
        hsplit(v, h, l);
        s_ah[m][k] = h;
        s_al[m][k] = l;
    }
    __syncthreads();

    const int r1 = lane >> 2;
    const int kb = (lane & 3) * 2;
    const int seg = lane >> 3, lx8 = lane & 7;
    const unsigned a_h_base = scvta(&s_ah[16 * wrp + (seg & 1) * 8 + lx8][(seg >> 1) * 8]);
    const unsigned a_l_base = scvta(&s_al[16 * wrp + (seg & 1) * 8 + lx8][(seg >> 1) * 8]);
    const int nrow0 = 8 * (seg >> 1) + lx8;
    const int bk0 = (seg & 1) * 8;
    const unsigned b_base = scvta(&s_w[nrow0][bk0]);

    float acc[4][4];
#pragma unroll
    for (int f = 0; f < 4; f++)
#pragma unroll
        for (int q = 0; q < 4; q++) acc[f][q] = 0.f;

#pragma unroll
    for (int ks = 0; ks < 2; ks++) {
        unsigned ah[4], al[4];
        ldsm4(ah, a_h_base + ks * 32);
        ldsm4(al, a_l_base + ks * 32);
#pragma unroll
        for (int fp = 0; fp < 4; fp += 2) {
            const unsigned boff = (unsigned)(fp * (8 * KP * 2) + ks * 32);
            unsigned bh[4];
            ldsm4(bh, b_base + boff);
            mma16816(acc[fp], ah, bh[0], bh[1]);
            mma16816(acc[fp], al, bh[0], bh[1]);
            mma16816(acc[fp + 1], ah, bh[2], bh[3]);
            mma16816(acc[fp + 1], al, bh[2], bh[3]);
        }
    }

    const int Py = py0 / 2 + wrp;
    const int Px = px0 / 2 + (r1 >> 1);
    const bool writer = ((r1 & 1) == 0);
#pragma unroll
    for (int f = 0; f < 4; f++) {
        int ch = nb0 + f * 8 + kb;
        float v0 = fmaxf(acc[f][0], acc[f][2]);
        float v1 = fmaxf(acc[f][1], acc[f][3]);
        float o0 = fmaxf(v0, __shfl_xor_sync(0xffffffffu, v0, 4));
        float o1 = fmaxf(v1, __shfl_xor_sync(0xffffffffu, v1, 4));
        if (writer) {
            o0 = fmaxf(o0 + bias[ch], 0.f);
            o1 = fmaxf(o1 + bias[ch + 1], 0.f);
            size_t a = (((size_t)nimg * 32 + Py) * 32 + Px) * CH_ + ch;
            __half h0, l0, h1, l1;
            hsplit(o0, h0, l0);
            hsplit(o1, h1, l1);
            *(__half2*)(Oh + a) = __halves2half2(h0, h1);
            *(__half2*)(Ol + a) = __halves2half2(l0, l1);
        }
    }
}

// ---------------------------------------------------------------------------
// Tensor-core conv3x3+bias+ReLU+maxpool2, IMGS images per block, fp16
// 2-product (Ah*W + Al*W). Weights single fp16, staged once per chunk.
// ---------------------------------------------------------------------------
template <int PP, int IMGS, bool OUT_CL>
__global__ void __launch_bounds__(128 * IMGS)
conv_mma(const __half* __restrict__ Ah, const __half* __restrict__ Al,
         const __half* __restrict__ Wt, const float* __restrict__ bias,
         __half* __restrict__ Oh, __half* __restrict__ Ol,
         float* __restrict__ Ocf) {
    constexpr int CIC = 32;
    constexpr int KP = 40;
    constexpr int NCH = CH_ / CIC;
    constexpr int PPo = PP / 2;
    constexpr int TX = PP / 8;
    constexpr int T = 128 * IMGS;
    constexpr int A_ELEMS = IMGS * 100 * KP;
    constexpr int W_ELEMS = 9 * 32 * KP;

    extern __shared__ __align__(16) __half smem[];
    __half* s_ah = smem;
    __half* s_al = s_ah + A_ELEMS;
    __half* s_w  = s_al + A_ELEMS;

    const int tid = threadIdx.x;
    const int wrp = tid >> 5, lane = tid & 31;
    const int im = wrp >> 2, w4 = wrp & 3;
    const int img0 = blockIdx.z * IMGS;
    const int nb0 = blockIdx.y * 32;
    const int ty = blockIdx.x / TX, tx = blockIdx.x % TX;
    const int py0 = ty * 8, px0 = tx * 8;

    const int r1 = lane >> 2;
    const int kb = (lane & 3) * 2;
    const int seg = lane >> 3, lx8 = lane & 7;
    const int ay = 2 * w4 + (seg & 1);
    const int akoff = (seg >> 1) * 8;
    const int nrow0 = 8 * (seg >> 1) + lx8;
    const int bk0 = (seg & 1) * 8;

    const unsigned a_h_base = scvta(&s_ah[(im * 100 + ay * 10 + lx8) * KP + akoff]);
    const unsigned a_l_base = scvta(&s_al[(im * 100 + ay * 10 + lx8) * KP + akoff]);
    const unsigned b_base   = scvta(&s_w[nrow0 * KP + bk0]);

    float acc[4][4];
#pragma unroll
    for (int f = 0; f < 4; f++)
#pragma unroll
        for (int q = 0; q < 4; q++) acc[f][q] = 0.f;

    for (int cc = 0; cc < NCH; cc++) {
        __syncthreads();
        // stage A for IMGS images (10x10 halo x 32ch, hi+lo), zero-padded
        for (int idx = tid; idx < IMGS * 400; idx += T) {
            int aim = idx / 400, rem = idx - aim * 400;
            int p = rem >> 2, q = rem & 3;
            int ly = p / 10, lx = p - ly * 10;
            int gy = py0 - 1 + ly, gx = px0 - 1 + lx;
            uint4 vh = make_uint4(0u, 0u, 0u, 0u), vl = vh;
            if ((unsigned)gy < (unsigned)PP && (unsigned)gx < (unsigned)PP) {
                size_t g = (((size_t)(img0 + aim) * PP + gy) * PP + gx) * CH_ +
                           cc * CIC + q * 8;
                vh = *(const uint4*)(Ah + g);
                vl = *(const uint4*)(Al + g);
            }
            int base = (aim * 100 + ly * 10 + lx) * KP + q * 8;
            *(uint4*)&s_ah[base] = vh;
            *(uint4*)&s_al[base] = vl;
        }
        // stage weights [tap][n32][32] (once for all IMGS images)
        for (int idx = tid; idx < 1152; idx += T) {
            int tap = idx >> 7, rem = idx & 127;
            int nn = rem >> 2, q = rem & 3;
            size_t g = ((size_t)tap * CH_ + nb0 + nn) * CH_ + cc * CIC + q * 8;
            *(uint4*)&s_w[(tap * 32 + nn) * KP + q * 8] = *(const uint4*)(Wt + g);
        }
        __syncthreads();

#pragma unroll
        for (int tap = 0; tap < 9; tap++) {
            const int ky = tap / 3, kx = tap % 3;
#pragma unroll
            for (int ks = 0; ks < 2; ks++) {
                const unsigned aoff = (unsigned)((ky * 10 + kx) * (KP * 2) + ks * 32);
                unsigned ah[4], al[4];
                ldsm4(ah, a_h_base + aoff);
                ldsm4(al, a_l_base + aoff);
#pragma unroll
                for (int fp = 0; fp < 4; fp += 2) {
                    const unsigned boff =
                        (unsigned)(tap * (32 * KP * 2) + fp * (8 * KP * 2) + ks * 32);
                    unsigned bh[4];
                    ldsm4(bh, b_base + boff);
                    mma16816(acc[fp], ah, bh[0], bh[1]);
                    mma16816(acc[fp], al, bh[0], bh[1]);
                    mma16816(acc[fp + 1], ah, bh[2], bh[3]);
                    mma16816(acc[fp + 1], al, bh[2], bh[3]);
                }
            }
        }
    }

    const int nimg = img0 + im;
    const int Py = py0 / 2 + w4;
    const int Px = px0 / 2 + (r1 >> 1);
    const bool writer = ((r1 & 1) == 0);
#pragma unroll
    for (int f = 0; f < 4; f++) {
        int ch = nb0 + f * 8 + kb;
        float v0 = fmaxf(acc[f][0], acc[f][2]);
        float v1 = fmaxf(acc[f][1], acc[f][3]);
        float o0 = fmaxf(v0, __shfl_xor_sync(0xffffffffu, v0, 4));
        float o1 = fmaxf(v1, __shfl_xor_sync(0xffffffffu, v1, 4));
        if (writer) {
            o0 = fmaxf(o0 + bias[ch], 0.f);
            o1 = fmaxf(o1 + bias[ch + 1], 0.f);
            if (OUT_CL) {
                size_t a = (((size_t)nimg * PPo + Py) * PPo + Px) * CH_ + ch;
                __half h0, l0, h1, l1;
                hsplit(o0, h0, l0);
                hsplit(o1, h1, l1);
                *(__half2*)(Oh + a) = __halves2half2(h0, h1);
                *(__half2*)(Ol + a) = __halves2half2(l0, l1);
            } else {
                size_t a = (((size_t)nimg * CH_ + ch) * PPo + Py) * PPo + Px;
                Ocf[a] = o0;
                Ocf[a + (size_t)PPo * PPo] = o1;
            }
        }
    }
}

// ---------------------------------------------------------------------------
// BatchNorm (batch stats) + affine + flatten.
// ---------------------------------------------------------------------------
__global__ void __launch_bounds__(256)
bn_flatten(const float* __restrict__ y4, const float* __restrict__ gamma,
           const float* __restrict__ beta, float* __restrict__ feat) {
    int c = blockIdx.x, tid = threadIdx.x;
    int i0 = tid * 4;
    int n = i0 >> 4, hw = i0 & 15;
    float4 v = *(const float4*)(y4 + (((size_t)n * 160 + c) << 4) + hw);
    float s = v.x + v.y + v.z + v.w;
    float q = v.x * v.x + v.y * v.y + v.z * v.z + v.w * v.w;
#pragma unroll
    for (int off = 16; off; off >>= 1) {
        s += __shfl_xor_sync(0xffffffffu, s, off);
        q += __shfl_xor_sync(0xffffffffu, q, off);
    }
    __shared__ float rs[8], rq[8];
    __shared__ float s_scale, s_shift;
    int w = tid >> 5, lane = tid & 31;
    if (!lane) { rs[w] = s; rq[w] = q; }
    __syncthreads();
    if (tid == 0) {
        float S = 0.f, Q = 0.f;
#pragma unroll
        for (int j = 0; j < 8; j++) { S += rs[j]; Q += rq[j]; }
        float mean = S * (1.f / 1024.f);
        float var = Q * (1.f / 1024.f) - mean * mean;
        float r = rsqrtf(var + EPS_);
        float g = gamma[c] * r;
        s_scale = g;
        s_shift = beta[c] - mean * g;
    }
    __syncthreads();
    float g = s_scale, b = s_shift;
    float4 o = make_float4(v.x * g + b, v.y * g + b, v.z * g + b, v.w * g + b);
    *(float4*)(feat + (size_t)n * 2560 + c * 16 + hw) = o;
}

// ---------------------------------------------------------------------------
// Routed linear: warp per output element.
// ---------------------------------------------------------------------------
template <bool RELU>
__global__ void __launch_bounds__(256)
fc_routed(const float* __restrict__ X, const float* __restrict__ Wb,
          const float* __restrict__ Bb, const int* __restrict__ act,
          float* __restrict__ Y, int IN, int OD) {
    int n = blockIdx.y;
    int w = threadIdx.x >> 5, lane = threadIdx.x & 31;
    int o = blockIdx.x * (blockDim.x >> 5) + w;
    if (o >= OD) return;
    int e = act[n];
    const float* wr = Wb + ((size_t)e * OD + o) * IN;
    const float* xr = X + (size_t)n * IN;
    float s = 0.f;
    for (int i = lane * 4; i < IN; i += 128) {
        float4 a = *(const float4*)(wr + i);
        float4 b = *(const float4*)(xr + i);
        s += a.x * b.x + a.y * b.y + a.z * b.z + a.w * b.w;
    }
#pragma unroll
    for (int off = 16; off; off >>= 1) s += __shfl_xor_sync(0xffffffffu, s, off);
    if (!lane) {
        float v = s + Bb[(size_t)e * OD + o];
        if (RELU) v = fmaxf(v, 0.f);
        Y[(size_t)n * OD + o] = v;
    }
}

// ---------------------------------------------------------------------------
extern "C" void kernel_launch(void* const* d_in, const int* in_sizes, int n_in,
                              void* d_out, int out_size) {
    const float* x   = (const float*)d_in[0];
    const int* a1    = (const int*)d_in[1];
    const int* a2    = (const int*)d_in[2];
    const int* a3    = (const int*)d_in[3];
    const float* W1  = (const float*)d_in[4];
    const float* b1  = (const float*)d_in[5];
    const float* W2  = (const float*)d_in[6];
    const float* b2  = (const float*)d_in[7];
    const float* W3  = (const float*)d_in[8];
    const float* b3  = (const float*)d_in[9];
    const float* W4  = (const float*)d_in[10];
    const float* b4  = (const float*)d_in[11];
    const float* gam = (const float*)d_in[12];
    const float* bet = (const float*)d_in[13];
    const float* E1W = (const float*)d_in[14];
    const float* E1b = (const float*)d_in[15];
    const float* E2W = (const float*)d_in[16];
    const float* E2b = (const float*)d_in[17];
    const float* E3W = (const float*)d_in[18];
    const float* E3b = (const float*)d_in[19];
    float* out = (float*)d_out;

    __half *y1h, *y1l, *y2h, *y2l, *y3h, *y3l, *w1, *w2, *w3, *w4;
    float *y4, *feat, *h1, *h2;
    cudaGetSymbolAddress((void**)&y1h, g_y1h);
    cudaGetSymbolAddress((void**)&y1l, g_y1l);
    cudaGetSymbolAddress((void**)&y2h, g_y2h);
    cudaGetSymbolAddress((void**)&y2l, g_y2l);
    cudaGetSymbolAddress((void**)&y3h, g_y3h);
    cudaGetSymbolAddress((void**)&y3l, g_y3l);
    cudaGetSymbolAddress((void**)&w1, g_w1);
    cudaGetSymbolAddress((void**)&w2, g_w2);
    cudaGetSymbolAddress((void**)&w3, g_w3);
    cudaGetSymbolAddress((void**)&w4, g_w4);
    cudaGetSymbolAddress((void**)&y4, g_y4);
    cudaGetSymbolAddress((void**)&feat, g_feat);
    cudaGetSymbolAddress((void**)&h1, g_h1);
    cudaGetSymbolAddress((void**)&h2, g_h2);

    // dynamic smem for conv_mma<*, 4, *>: (2*16000 + 11520) half elems
    constexpr int SMEM_CONV = (2 * (4 * 100 * 40) + 9 * 32 * 40) * 2;  // 87040
    static bool attr_set = false;
    if (!attr_set) {
        cudaFuncSetAttribute(conv_mma<32, 4, true>,
                             cudaFuncAttributeMaxDynamicSharedMemorySize, SMEM_CONV);
        cudaFuncSetAttribute(conv_mma<16, 4, true>,
                             cudaFuncAttributeMaxDynamicSharedMemorySize, SMEM_CONV);
        cudaFuncSetAttribute(conv_mma<8, 4, false>,
                             cudaFuncAttributeMaxDynamicSharedMemorySize, SMEM_CONV);
        attr_set = true;
    }

    // weight converts (one merged launch for W2/W3/W4 + tiny W1)
    pre_w<<<dim3((9 * CH_ * CH_ + 255) / 256, 3), 256>>>(W2, W3, W4, w2, w3, w4);
    pre_w1<<<(CH_ * 32 + 255) / 256, 256>>>(W1, w1);

    // conv1 tensor (im2col): 64x64 -> pooled 32x32
    conv1_mma<<<dim3(64, 5, 64), 128>>>(x, w1, b1, y1h, y1l);
    // conv2 tensor, 4 images/block: 32x32 prepool -> 16x16
    conv_mma<32, 4, true><<<dim3(16, 5, 16), 512, SMEM_CONV>>>(
        y1h, y1l, w2, b2, y2h, y2l, nullptr);
    // conv3 tensor, 4 images/block: 16x16 prepool -> 8x8
    conv_mma<16, 4, true><<<dim3(4, 5, 16), 512, SMEM_CONV>>>(
        y2h, y2l, w3, b3, y3h, y3l, nullptr);
    // conv4 tensor, 4 images/block: 8x8 prepool -> 4x4, fp32 chan-first out
    conv_mma<8, 4, false><<<dim3(1, 5, 16), 512, SMEM_CONV>>>(
        y3h, y3l, w4, b4, nullptr, nullptr, y4);

    bn_flatten<<<160, 256>>>(y4, gam, bet, feat);

    fc_routed<true ><<<dim3(40, 64), 256>>>(feat, E1W, E1b, a1, h1, 2560, 320);
    fc_routed<true ><<<dim3(40, 64), 256>>>(h1,   E2W, E2b, a2, h2, 320, 320);
    fc_routed<false><<<dim3(2, 64),  256>>>(h2,   E3W, E3b, a3, out, 320, 10);
}

// round 14
// speedup vs baseline: 3.5516x; 1.1069x over previous
#include <cuda_runtime.h>
#include <cuda_fp16.h>
#include <cstdint>
#include <cstddef>

// ---------------------------------------------------------------------------
// RoutedAllFC round 14: accuracy margin + LSU relief.
//  - conv1/conv3/conv4: 3-product fp16 (A hi/lo x Wh + Ah x Wl) -> weight
//    rounding corrected; conv2 (dominant) stays 2-product.
//  - cp.async (LDGSTS) staging in conv_mma (halves staging LSU ops).
//  - conv1: one block computes all 160 co (im2col built once).
//  - conv3/conv4: IMGS=2, 78KB smem -> 2 blocks/SM, better chip fill.
// ---------------------------------------------------------------------------

#define B_   64
#define CH_  160
#define EPS_ 1e-5f

// activations, channel-last fp16 hi/lo splits
__device__ __half g_y1h[B_ * 32 * 32 * CH_];
__device__ __half g_y1l[B_ * 32 * 32 * CH_];
__device__ __half g_y2h[B_ * 16 * 16 * CH_];
__device__ __half g_y2l[B_ * 16 * 16 * CH_];
__device__ __half g_y3h[B_ * 8 * 8 * CH_];
__device__ __half g_y3l[B_ * 8 * 8 * CH_];
// weights fp16 hi/lo
__device__ __half g_w1h[CH_ * 32];
__device__ __half g_w1l[CH_ * 32];
__device__ __half g_w2h[9 * CH_ * CH_];   // [tap][co][ci] (lo unused for conv2)
__device__ __half g_w2l[9 * CH_ * CH_];
__device__ __half g_w3h[9 * CH_ * CH_];
__device__ __half g_w3l[9 * CH_ * CH_];
__device__ __half g_w4h[9 * CH_ * CH_];
__device__ __half g_w4l[9 * CH_ * CH_];
// fp32 tail
__device__ float g_y4[B_ * CH_ * 4 * 4];
__device__ float g_feat[B_ * 2560];
__device__ float g_h1[B_ * 320];
__device__ float g_h2[B_ * 320];

// ---- fp16 split --------------------------------------------------------------
__device__ __forceinline__ void hsplit(float v, __half& h, __half& l) {
    h = __float2half_rn(v);
    l = __float2half_rn(v - __half2float(h));
}

// ---- mma / ldmatrix / cp.async -----------------------------------------------
__device__ __forceinline__ void mma16816(float* c, const unsigned* a,
                                         unsigned b0, unsigned b1) {
    asm("mma.sync.aligned.m16n8k16.row.col.f32.f16.f16.f32 "
        "{%0,%1,%2,%3},{%4,%5,%6,%7},{%8,%9},{%0,%1,%2,%3};"
        : "+f"(c[0]), "+f"(c[1]), "+f"(c[2]), "+f"(c[3])
        : "r"(a[0]), "r"(a[1]), "r"(a[2]), "r"(a[3]), "r"(b0), "r"(b1));
}
__device__ __forceinline__ void ldsm4(unsigned* r, unsigned addr) {
    asm volatile("ldmatrix.sync.aligned.m8n8.x4.shared.b16 {%0,%1,%2,%3}, [%4];"
                 : "=r"(r[0]), "=r"(r[1]), "=r"(r[2]), "=r"(r[3]) : "r"(addr));
}
__device__ __forceinline__ unsigned scvta(const void* p) {
    return (unsigned)__cvta_generic_to_shared(p);
}
__device__ __forceinline__ void cpasync16(unsigned dst, const void* src, int ss) {
    asm volatile("cp.async.cg.shared.global [%0], [%1], 16, %2;"
                 :: "r"(dst), "l"(src), "r"(ss));
}
__device__ __forceinline__ void cpasync_wait() {
    asm volatile("cp.async.commit_group;");
    asm volatile("cp.async.wait_group 0;");
}

// ---------------------------------------------------------------------------
// weight pre-splits (fp32 [co][ci][3][3] -> fp16 h/l [tap][co][ci])
// ---------------------------------------------------------------------------
__global__ void __launch_bounds__(256)
pre_w(const float* __restrict__ W2, const float* __restrict__ W3,
      const float* __restrict__ W4,
      __half* __restrict__ O2h, __half* __restrict__ O2l,
      __half* __restrict__ O3h, __half* __restrict__ O3l,
      __half* __restrict__ O4h, __half* __restrict__ O4l) {
    int idx = blockIdx.x * 256 + threadIdx.x;
    if (idx >= 9 * CH_ * CH_) return;
    const float* W = (blockIdx.y == 0) ? W2 : (blockIdx.y == 1) ? W3 : W4;
    __half* Oh = (blockIdx.y == 0) ? O2h : (blockIdx.y == 1) ? O3h : O4h;
    __half* Ol = (blockIdx.y == 0) ? O2l : (blockIdx.y == 1) ? O3l : O4l;
    int tap = idx / (CH_ * CH_);
    int r = idx - tap * (CH_ * CH_);
    int co = r / CH_, ci = r - co * CH_;
    __half h, l;
    hsplit(W[(co * CH_ + ci) * 9 + tap], h, l);
    Oh[idx] = h;
    Ol[idx] = l;
}

__global__ void __launch_bounds__(256)
pre_w1(const float* __restrict__ W, __half* __restrict__ Oh,
       __half* __restrict__ Ol) {
    int idx = blockIdx.x * 256 + threadIdx.x;
    if (idx >= CH_ * 32) return;
    int co = idx >> 5, k = idx & 31;
    __half h, l;
    hsplit((k < 27) ? W[co * 27 + k] : 0.f, h, l);
    Oh[idx] = h;
    Ol[idx] = l;
}

// ---------------------------------------------------------------------------
// conv1: im2col GEMM, one block = one 8x8-prepool tile x ALL 160 co.
// 3-product fp16. M=64, N=160, K=32 (27 real).
// ---------------------------------------------------------------------------
__global__ void __launch_bounds__(128)
conv1_mma(const float* __restrict__ x,
          const __half* __restrict__ Wh, const __half* __restrict__ Wl,
          const float* __restrict__ bias,
          __half* __restrict__ Oh, __half* __restrict__ Ol) {
    constexpr int KP = 40;
    __shared__ float s_halo[3][10][10];
    __shared__ alignas(16) __half s_ah[64][KP];
    __shared__ alignas(16) __half s_al[64][KP];
    __shared__ alignas(16) __half s_wh[160][KP];
    __shared__ alignas(16) __half s_wl[160][KP];

    const int tid = threadIdx.x;
    const int wrp = tid >> 5, lane = tid & 31;
    const int nimg = blockIdx.y;
    const int ty = blockIdx.x >> 3, tx = blockIdx.x & 7;
    const int py0 = ty * 8, px0 = tx * 8;

    for (int idx = tid; idx < 300; idx += 128) {
        int ci = idx / 100, rem = idx - ci * 100;
        int ly = rem / 10, lx = rem - ly * 10;
        int gy = py0 - 1 + ly, gx = px0 - 1 + lx;
        float v = 0.f;
        if ((unsigned)gy < 64u && (unsigned)gx < 64u)
            v = x[(((size_t)nimg * 3 + ci) * 64 + gy) * 64 + gx];
        s_halo[ci][ly][lx] = v;
    }
    // weights [160][32] h+l via uint4 (4 x 16B per row)
    for (int idx = tid; idx < 640; idx += 128) {
        int nn = idx >> 2, q = idx & 3;
        *(uint4*)&s_wh[nn][q * 8] = *(const uint4*)(Wh + nn * 32 + q * 8);
        *(uint4*)&s_wl[nn][q * 8] = *(const uint4*)(Wl + nn * 32 + q * 8);
    }
    __syncthreads();

    for (int idx = tid; idx < 2048; idx += 128) {
        int m = idx >> 5, k = idx & 31;
        int yy = m >> 3, xx = m & 7;
        float v = 0.f;
        if (k < 27) {
            int ci = k / 9, tap = k - ci * 9;
            int ky = tap / 3, kx = tap - ky * 3;
            v = s_halo[ci][yy + ky][xx + kx];
        }
        __half h, l;
        hsplit(v, h, l);
        s_ah[m][k] = h;
        s_al[m][k] = l;
    }
    __syncthreads();

    const int r1 = lane >> 2;
    const int kb = (lane & 3) * 2;
    const int seg = lane >> 3, lx8 = lane & 7;
    const unsigned a_h_base = scvta(&s_ah[16 * wrp + (seg & 1) * 8 + lx8][(seg >> 1) * 8]);
    const unsigned a_l_base = scvta(&s_al[16 * wrp + (seg & 1) * 8 + lx8][(seg >> 1) * 8]);
    const int nrow0 = 8 * (seg >> 1) + lx8;
    const int bk0 = (seg & 1) * 8;
    const unsigned b_h_base = scvta(&s_wh[nrow0][bk0]);
    const unsigned b_l_base = scvta(&s_wl[nrow0][bk0]);

    float acc[20][4];
#pragma unroll
    for (int f = 0; f < 20; f++)
#pragma unroll
        for (int q = 0; q < 4; q++) acc[f][q] = 0.f;

#pragma unroll
    for (int ks = 0; ks < 2; ks++) {
        unsigned ah[4], al[4];
        ldsm4(ah, a_h_base + ks * 32);
        ldsm4(al, a_l_base + ks * 32);
#pragma unroll
        for (int fp = 0; fp < 20; fp += 2) {
            const unsigned boff = (unsigned)(fp * (8 * KP * 2) + ks * 32);
            unsigned bh[4], bl[4];
            ldsm4(bh, b_h_base + boff);
            ldsm4(bl, b_l_base + boff);
            mma16816(acc[fp], ah, bh[0], bh[1]);
            mma16816(acc[fp], al, bh[0], bh[1]);
            mma16816(acc[fp], ah, bl[0], bl[1]);
            mma16816(acc[fp + 1], ah, bh[2], bh[3]);
            mma16816(acc[fp + 1], al, bh[2], bh[3]);
            mma16816(acc[fp + 1], ah, bl[2], bl[3]);
        }
    }

    const int Py = py0 / 2 + wrp;
    const int Px = px0 / 2 + (r1 >> 1);
    const bool writer = ((r1 & 1) == 0);
#pragma unroll
    for (int f = 0; f < 20; f++) {
        int ch = f * 8 + kb;
        float v0 = fmaxf(acc[f][0], acc[f][2]);
        float v1 = fmaxf(acc[f][1], acc[f][3]);
        float o0 = fmaxf(v0, __shfl_xor_sync(0xffffffffu, v0, 4));
        float o1 = fmaxf(v1, __shfl_xor_sync(0xffffffffu, v1, 4));
        if (writer) {
            o0 = fmaxf(o0 + bias[ch], 0.f);
            o1 = fmaxf(o1 + bias[ch + 1], 0.f);
            size_t a = (((size_t)nimg * 32 + Py) * 32 + Px) * CH_ + ch;
            __half h0, l0, h1, l1;
            hsplit(o0, h0, l0);
            hsplit(o1, h1, l1);
            *(__half2*)(Oh + a) = __halves2half2(h0, h1);
            *(__half2*)(Ol + a) = __halves2half2(l0, l1);
        }
    }
}

// ---------------------------------------------------------------------------
// Tensor-core conv3x3+bias+ReLU+maxpool2, IMGS images/block, NPROD in {2,3}.
// cp.async staging. NPROD==3 adds Ah*Wl correction (weight rounding fixed).
// ---------------------------------------------------------------------------
template <int PP, int IMGS, int NPROD, bool OUT_CL>
__global__ void __launch_bounds__(128 * IMGS)
conv_mma(const __half* __restrict__ Ah, const __half* __restrict__ Al,
         const __half* __restrict__ Wth, const __half* __restrict__ Wtl,
         const float* __restrict__ bias,
         __half* __restrict__ Oh, __half* __restrict__ Ol,
         float* __restrict__ Ocf) {
    constexpr int CIC = 32;
    constexpr int KP = 40;
    constexpr int NCH = CH_ / CIC;
    constexpr int PPo = PP / 2;
    constexpr int TX = PP / 8;
    constexpr int T = 128 * IMGS;
    constexpr int A_ELEMS = IMGS * 100 * KP;
    constexpr int W_ELEMS = 9 * 32 * KP;

    extern __shared__ __align__(16) __half smem[];
    __half* s_ah = smem;
    __half* s_al = s_ah + A_ELEMS;
    __half* s_wh = s_al + A_ELEMS;
    __half* s_wl = s_wh + W_ELEMS;   // only populated when NPROD==3

    const int tid = threadIdx.x;
    const int wrp = tid >> 5, lane = tid & 31;
    const int im = wrp >> 2, w4 = wrp & 3;
    const int img0 = blockIdx.z * IMGS;
    const int nb0 = blockIdx.y * 32;
    const int ty = blockIdx.x / TX, tx = blockIdx.x % TX;
    const int py0 = ty * 8, px0 = tx * 8;

    const int r1 = lane >> 2;
    const int kb = (lane & 3) * 2;
    const int seg = lane >> 3, lx8 = lane & 7;
    const int ay = 2 * w4 + (seg & 1);
    const int akoff = (seg >> 1) * 8;
    const int nrow0 = 8 * (seg >> 1) + lx8;
    const int bk0 = (seg & 1) * 8;

    const unsigned a_h_base = scvta(&s_ah[(im * 100 + ay * 10 + lx8) * KP + akoff]);
    const unsigned a_l_base = scvta(&s_al[(im * 100 + ay * 10 + lx8) * KP + akoff]);
    const unsigned b_h_base = scvta(&s_wh[nrow0 * KP + bk0]);
    const unsigned b_l_base = scvta(&s_wl[nrow0 * KP + bk0]);

    float acc[4][4];
#pragma unroll
    for (int f = 0; f < 4; f++)
#pragma unroll
        for (int q = 0; q < 4; q++) acc[f][q] = 0.f;

    for (int cc = 0; cc < NCH; cc++) {
        __syncthreads();
        // A staging via cp.async (zero-fill OOB with src-size 0)
        for (int idx = tid; idx < IMGS * 400; idx += T) {
            int aim = idx / 400, rem = idx - aim * 400;
            int p = rem >> 2, q = rem & 3;
            int ly = p / 10, lx = p - ly * 10;
            int gy = py0 - 1 + ly, gx = px0 - 1 + lx;
            bool ok = (unsigned)gy < (unsigned)PP && (unsigned)gx < (unsigned)PP;
            size_t g = ok ? ((((size_t)(img0 + aim) * PP + gy) * PP + gx) * CH_ +
                             cc * CIC + q * 8)
                          : 0;
            int ss = ok ? 16 : 0;
            int base = (aim * 100 + ly * 10 + lx) * KP + q * 8;
            cpasync16(scvta(&s_ah[base]), Ah + g, ss);
            cpasync16(scvta(&s_al[base]), Al + g, ss);
        }
        // W staging via cp.async
        for (int idx = tid; idx < 1152; idx += T) {
            int tap = idx >> 7, rem = idx & 127;
            int nn = rem >> 2, q = rem & 3;
            size_t g = ((size_t)tap * CH_ + nb0 + nn) * CH_ + cc * CIC + q * 8;
            int base = (tap * 32 + nn) * KP + q * 8;
            cpasync16(scvta(&s_wh[base]), Wth + g, 16);
            if (NPROD == 3)
                cpasync16(scvta(&s_wl[base]), Wtl + g, 16);
        }
        cpasync_wait();
        __syncthreads();

#pragma unroll
        for (int tap = 0; tap < 9; tap++) {
            const int ky = tap / 3, kx = tap % 3;
#pragma unroll
            for (int ks = 0; ks < 2; ks++) {
                const unsigned aoff = (unsigned)((ky * 10 + kx) * (KP * 2) + ks * 32);
                unsigned ah[4], al[4];
                ldsm4(ah, a_h_base + aoff);
                ldsm4(al, a_l_base + aoff);
#pragma unroll
                for (int fp = 0; fp < 4; fp += 2) {
                    const unsigned boff =
                        (unsigned)(tap * (32 * KP * 2) + fp * (8 * KP * 2) + ks * 32);
                    unsigned bh[4];
                    ldsm4(bh, b_h_base + boff);
                    mma16816(acc[fp], ah, bh[0], bh[1]);
                    mma16816(acc[fp], al, bh[0], bh[1]);
                    mma16816(acc[fp + 1], ah, bh[2], bh[3]);
                    mma16816(acc[fp + 1], al, bh[2], bh[3]);
                    if (NPROD == 3) {
                        unsigned bl[4];
                        ldsm4(bl, b_l_base + boff);
                        mma16816(acc[fp], ah, bl[0], bl[1]);
                        mma16816(acc[fp + 1], ah, bl[2], bl[3]);
                    }
                }
            }
        }
    }

    const int nimg = img0 + im;
    const int Py = py0 / 2 + w4;
    const int Px = px0 / 2 + (r1 >> 1);
    const bool writer = ((r1 & 1) == 0);
#pragma unroll
    for (int f = 0; f < 4; f++) {
        int ch = nb0 + f * 8 + kb;
        float v0 = fmaxf(acc[f][0], acc[f][2]);
        float v1 = fmaxf(acc[f][1], acc[f][3]);
        float o0 = fmaxf(v0, __shfl_xor_sync(0xffffffffu, v0, 4));
        float o1 = fmaxf(v1, __shfl_xor_sync(0xffffffffu, v1, 4));
        if (writer) {
            o0 = fmaxf(o0 + bias[ch], 0.f);
            o1 = fmaxf(o1 + bias[ch + 1], 0.f);
            if (OUT_CL) {
                size_t a = (((size_t)nimg * PPo + Py) * PPo + Px) * CH_ + ch;
                __half h0, l0, h1, l1;
                hsplit(o0, h0, l0);
                hsplit(o1, h1, l1);
                *(__half2*)(Oh + a) = __halves2half2(h0, h1);
                *(__half2*)(Ol + a) = __halves2half2(l0, l1);
            } else {
                size_t a = (((size_t)nimg * CH_ + ch) * PPo + Py) * PPo + Px;
                Ocf[a] = o0;
                Ocf[a + (size_t)PPo * PPo] = o1;
            }
        }
    }
}

// ---------------------------------------------------------------------------
// BatchNorm (batch stats) + affine + flatten.
// ---------------------------------------------------------------------------
__global__ void __launch_bounds__(256)
bn_flatten(const float* __restrict__ y4, const float* __restrict__ gamma,
           const float* __restrict__ beta, float* __restrict__ feat) {
    int c = blockIdx.x, tid = threadIdx.x;
    int i0 = tid * 4;
    int n = i0 >> 4, hw = i0 & 15;
    float4 v = *(const float4*)(y4 + (((size_t)n * 160 + c) << 4) + hw);
    float s = v.x + v.y + v.z + v.w;
    float q = v.x * v.x + v.y * v.y + v.z * v.z + v.w * v.w;
#pragma unroll
    for (int off = 16; off; off >>= 1) {
        s += __shfl_xor_sync(0xffffffffu, s, off);
        q += __shfl_xor_sync(0xffffffffu, q, off);
    }
    __shared__ float rs[8], rq[8];
    __shared__ float s_scale, s_shift;
    int w = tid >> 5, lane = tid & 31;
    if (!lane) { rs[w] = s; rq[w] = q; }
    __syncthreads();
    if (tid == 0) {
        float S = 0.f, Q = 0.f;
#pragma unroll
        for (int j = 0; j < 8; j++) { S += rs[j]; Q += rq[j]; }
        float mean = S * (1.f / 1024.f);
        float var = Q * (1.f / 1024.f) - mean * mean;
        float r = rsqrtf(var + EPS_);
        float g = gamma[c] * r;
        s_scale = g;
        s_shift = beta[c] - mean * g;
    }
    __syncthreads();
    float g = s_scale, b = s_shift;
    float4 o = make_float4(v.x * g + b, v.y * g + b, v.z * g + b, v.w * g + b);
    *(float4*)(feat + (size_t)n * 2560 + c * 16 + hw) = o;
}

// ---------------------------------------------------------------------------
// Routed linear: warp per output element.
// ---------------------------------------------------------------------------
template <bool RELU>
__global__ void __launch_bounds__(256)
fc_routed(const float* __restrict__ X, const float* __restrict__ Wb,
          const float* __restrict__ Bb, const int* __restrict__ act,
          float* __restrict__ Y, int IN, int OD) {
    int n = blockIdx.y;
    int w = threadIdx.x >> 5, lane = threadIdx.x & 31;
    int o = blockIdx.x * (blockDim.x >> 5) + w;
    if (o >= OD) return;
    int e = act[n];
    const float* wr = Wb + ((size_t)e * OD + o) * IN;
    const float* xr = X + (size_t)n * IN;
    float s = 0.f;
    for (int i = lane * 4; i < IN; i += 128) {
        float4 a = *(const float4*)(wr + i);
        float4 b = *(const float4*)(xr + i);
        s += a.x * b.x + a.y * b.y + a.z * b.z + a.w * b.w;
    }
#pragma unroll
    for (int off = 16; off; off >>= 1) s += __shfl_xor_sync(0xffffffffu, s, off);
    if (!lane) {
        float v = s + Bb[(size_t)e * OD + o];
        if (RELU) v = fmaxf(v, 0.f);
        Y[(size_t)n * OD + o] = v;
    }
}

// ---------------------------------------------------------------------------
extern "C" void kernel_launch(void* const* d_in, const int* in_sizes, int n_in,
                              void* d_out, int out_size) {
    const float* x   = (const float*)d_in[0];
    const int* a1    = (const int*)d_in[1];
    const int* a2    = (const int*)d_in[2];
    const int* a3    = (const int*)d_in[3];
    const float* W1  = (const float*)d_in[4];
    const float* b1  = (const float*)d_in[5];
    const float* W2  = (const float*)d_in[6];
    const float* b2  = (const float*)d_in[7];
    const float* W3  = (const float*)d_in[8];
    const float* b3  = (const float*)d_in[9];
    const float* W4  = (const float*)d_in[10];
    const float* b4  = (const float*)d_in[11];
    const float* gam = (const float*)d_in[12];
    const float* bet = (const float*)d_in[13];
    const float* E1W = (const float*)d_in[14];
    const float* E1b = (const float*)d_in[15];
    const float* E2W = (const float*)d_in[16];
    const float* E2b = (const float*)d_in[17];
    const float* E3W = (const float*)d_in[18];
    const float* E3b = (const float*)d_in[19];
    float* out = (float*)d_out;

    __half *y1h, *y1l, *y2h, *y2l, *y3h, *y3l;
    __half *w1h, *w1l, *w2h, *w2l, *w3h, *w3l, *w4h, *w4l;
    float *y4, *feat, *h1, *h2;
    cudaGetSymbolAddress((void**)&y1h, g_y1h);
    cudaGetSymbolAddress((void**)&y1l, g_y1l);
    cudaGetSymbolAddress((void**)&y2h, g_y2h);
    cudaGetSymbolAddress((void**)&y2l, g_y2l);
    cudaGetSymbolAddress((void**)&y3h, g_y3h);
    cudaGetSymbolAddress((void**)&y3l, g_y3l);
    cudaGetSymbolAddress((void**)&w1h, g_w1h);
    cudaGetSymbolAddress((void**)&w1l, g_w1l);
    cudaGetSymbolAddress((void**)&w2h, g_w2h);
    cudaGetSymbolAddress((void**)&w2l, g_w2l);
    cudaGetSymbolAddress((void**)&w3h, g_w3h);
    cudaGetSymbolAddress((void**)&w3l, g_w3l);
    cudaGetSymbolAddress((void**)&w4h, g_w4h);
    cudaGetSymbolAddress((void**)&w4l, g_w4l);
    cudaGetSymbolAddress((void**)&y4, g_y4);
    cudaGetSymbolAddress((void**)&feat, g_feat);
    cudaGetSymbolAddress((void**)&h1, g_h1);
    cudaGetSymbolAddress((void**)&h2, g_h2);

    // dynamic smem: conv2 <32,4,2>: 2*A + 1*W (wl slot unused);
    // conv3/4 <*,2,3>: 2*A(IMGS=2) + 2*W
    constexpr int SMEM_C2 = (2 * (4 * 100 * 40) + 9 * 32 * 40) * 2;      // 87040
    constexpr int SMEM_C34 = (2 * (2 * 100 * 40) + 2 * (9 * 32 * 40)) * 2;  // 78080
    static bool attr_set = false;
    if (!attr_set) {
        cudaFuncSetAttribute(conv_mma<32, 4, 2, true>,
                             cudaFuncAttributeMaxDynamicSharedMemorySize, SMEM_C2);
        cudaFuncSetAttribute(conv_mma<16, 2, 3, true>,
                             cudaFuncAttributeMaxDynamicSharedMemorySize, SMEM_C34);
        cudaFuncSetAttribute(conv_mma<8, 2, 3, false>,
                             cudaFuncAttributeMaxDynamicSharedMemorySize, SMEM_C34);
        attr_set = true;
    }

    // weight pre-splits
    pre_w<<<dim3((9 * CH_ * CH_ + 255) / 256, 3), 256>>>(
        W2, W3, W4, w2h, w2l, w3h, w3l, w4h, w4l);
    pre_w1<<<(CH_ * 32 + 255) / 256, 256>>>(W1, w1h, w1l);

    // conv1: all-co im2col GEMM, 3-product. 64x64 -> pooled 32x32
    conv1_mma<<<dim3(64, 64), 128>>>(x, w1h, w1l, b1, y1h, y1l);
    // conv2: 4 images/block, 2-product (dominant layer)
    conv_mma<32, 4, 2, true><<<dim3(16, 5, 16), 512, SMEM_C2>>>(
        y1h, y1l, w2h, nullptr, b2, y2h, y2l, nullptr);
    // conv3: 2 images/block, 3-product
    conv_mma<16, 2, 3, true><<<dim3(4, 5, 32), 256, SMEM_C34>>>(
        y2h, y2l, w3h, w3l, b3, y3h, y3l, nullptr);
    // conv4: 2 images/block, 3-product, fp32 chan-first out
    conv_mma<8, 2, 3, false><<<dim3(1, 5, 32), 256, SMEM_C34>>>(
        y3h, y3l, w4h, w4l, b4, nullptr, nullptr, y4);

    bn_flatten<<<160, 256>>>(y4, gam, bet, feat);

    fc_routed<true ><<<dim3(40, 64), 256>>>(feat, E1W, E1b, a1, h1, 2560, 320);
    fc_routed<true ><<<dim3(40, 64), 256>>>(h1,   E2W, E2b, a2, h2, 320, 320);
    fc_routed<false><<<dim3(2, 64),  256>>>(h2,   E3W, E3b, a3, out, 320, 10);
}